// round 10
// baseline (speedup 1.0000x reference)
#include <cuda_runtime.h>
#include <cuda_bf16.h>

#define BS 131072
#define PLEN 10
#define NCH1 23   // GEMM1: K=361 padded to 368 = 23 chunks of 16

// -------- pre-split weights: packed bf16 (2 per u32 along k), hi & lo parts.
// W1/W2/W3: natural order (scalar B loads at +tg/+tg+4, as in the 899us kernel).
// Whh ONLY: within each aligned group of 8 u32, indices permuted so the (B0,B1)
// mma pair (orig u32 tg, tg+4) sits at adjacent slots 2tg, 2tg+1 (uint2 loads).
__device__ __align__(16) unsigned g_W1h[NCH1 * 256 * 8], g_W1l[NCH1 * 256 * 8]; // [kc][n][8]
__device__ __align__(16) unsigned g_W2h[4 * 128 * 32],   g_W2l[4 * 128 * 32];   // [kc][n][32]
__device__ __align__(16) unsigned g_W3h[64 * 64],        g_W3l[64 * 64];        // [n][64]
__device__ __align__(16) unsigned g_Whh[192 * 32],       g_Whl[192 * 32];       // [n][32] permuted

// ---------------------------------------------------------------------------
__device__ __forceinline__ unsigned packbf(float lo, float hi) {
    unsigned r;
    asm("cvt.rn.bf16x2.f32 %0, %1, %2;" : "=r"(r) : "f"(hi), "f"(lo));
    return r;
}
__device__ __forceinline__ void split2(float v0, float v1, unsigned& hi, unsigned& lo) {
    hi = packbf(v0, v1);
    float h0 = __uint_as_float(hi << 16);
    float h1 = __uint_as_float(hi & 0xffff0000u);
    lo = packbf(v0 - h0, v1 - h1);
}
__device__ __forceinline__ float bflo(unsigned u) { return __uint_as_float(u << 16); }
__device__ __forceinline__ float bfhi(unsigned u) { return __uint_as_float(u & 0xffff0000u); }
__device__ __forceinline__ float relu_(float v) { return v > 0.f ? v : 0.f; }

__device__ __forceinline__ void mma16(float* c, const unsigned* a, unsigned b0, unsigned b1) {
    asm("mma.sync.aligned.m16n8k16.row.col.f32.bf16.bf16.f32 "
        "{%0,%1,%2,%3},{%4,%5,%6,%7},{%8,%9},{%0,%1,%2,%3};"
        : "+f"(c[0]), "+f"(c[1]), "+f"(c[2]), "+f"(c[3])
        : "r"(a[0]), "r"(a[1]), "r"(a[2]), "r"(a[3]), "r"(b0), "r"(b1));
}

__device__ __forceinline__ void cpa4(void* s, const void* g) {
    unsigned a = (unsigned)__cvta_generic_to_shared(s);
    asm volatile("cp.async.ca.shared.global [%0],[%1],4;" :: "r"(a), "l"(g) : "memory");
}
__device__ __forceinline__ void cpa16(void* s, const void* g) {
    unsigned a = (unsigned)__cvta_generic_to_shared(s);
    asm volatile("cp.async.cg.shared.global [%0],[%1],16;" :: "r"(a), "l"(g) : "memory");
}
__device__ __forceinline__ void cp_commit() { asm volatile("cp.async.commit_group;" ::: "memory"); }
template <int N>
__device__ __forceinline__ void cp_wait() { asm volatile("cp.async.wait_group %0;" :: "n"(N) : "memory"); }

// load fp32 A tile fragment (16 rows) and split to bf16 hi/lo frags
__device__ __forceinline__ void ldA_f32(const float* base, int stride, int g, int tg,
                                        unsigned* Ah, unsigned* Al) {
    float2 p0 = *(const float2*)(base + g * stride + 2 * tg);
    float2 p1 = *(const float2*)(base + (g + 8) * stride + 2 * tg);
    float2 p2 = *(const float2*)(base + g * stride + 2 * tg + 8);
    float2 p3 = *(const float2*)(base + (g + 8) * stride + 2 * tg + 8);
    split2(p0.x, p0.y, Ah[0], Al[0]);
    split2(p1.x, p1.y, Ah[1], Al[1]);
    split2(p2.x, p2.y, Ah[2], Al[2]);
    split2(p3.x, p3.y, Ah[3], Al[3]);
}

// stored index s (within 8-group) -> original u32 index (for permuted Whh)
__device__ __forceinline__ int inv_perm8(int s) {
    return (s & ~7) + ((s & 7) >> 1) + (s & 1) * 4;
}

// ---------------------------------------------------------------------------
// prep kernel: fp32 weights -> packed bf16 hi/lo global scratch
// elems = 47104 + 16384 + 4096 + 6144 = 73728 = 288 * 256
// ---------------------------------------------------------------------------
__global__ void prep_kernel(const float* __restrict__ W1, const float* __restrict__ W2,
                            const float* __restrict__ W3, const float* __restrict__ Whh) {
    int i = blockIdx.x * 256 + threadIdx.x;
    const int N1 = NCH1 * 256 * 8, N2 = 4 * 128 * 32, N3 = 64 * 64, N4 = 192 * 32;
    if (i < N1) {
        int kc = i >> 11, rem = i & 2047, n = rem >> 3, u = rem & 7;
        int k = kc * 16 + 2 * u;
        float v0 = (k < 361)     ? W1[n * 361 + k]     : 0.f;
        float v1 = (k + 1 < 361) ? W1[n * 361 + k + 1] : 0.f;
        split2(v0, v1, g_W1h[i], g_W1l[i]);
    } else if (i < N1 + N2) {
        int j = i - N1;
        int kc = j >> 12, rem = j & 4095, n = rem >> 5, u = rem & 31;
        int k = kc * 64 + 2 * u;
        split2(W2[n * 256 + k], W2[n * 256 + k + 1], g_W2h[j], g_W2l[j]);
    } else if (i < N1 + N2 + N3) {
        int j = i - N1 - N2;
        int n = j >> 6, u = j & 63;
        int k = 2 * u;
        split2(W3[n * 128 + k], W3[n * 128 + k + 1], g_W3h[j], g_W3l[j]);
    } else if (i < N1 + N2 + N3 + N4) {
        int j = i - N1 - N2 - N3;
        int n = j >> 5, s = j & 31;
        int k = 2 * inv_perm8(s);   // permuted pairs for uint2 B loads
        split2(Whh[n * 64 + k], Whh[n * 64 + k + 1], g_Whh[j], g_Whl[j]);
    }
}

// ---------------------------------------------------------------------------
// fused kernel: MLP (exact 899us structure) + improved GRU. 128 rows/CTA, 512 thr.
// smem (u32 units), peak 53380 = 213520 B:
//  h1hi [128][132] @0, h1lo @16896                                  (..33792)
//  P1: zbuf 2x[128][20] @33792, w1h 2x[256][12] @38912, w1l @45056  (..51200)
//  P2: w2h 2x[128][36] @33792, w2l @43008                           (..50304)
//  P3: w3h [64][68] @0, w3l @4352; h2hi [128][68] @33792, h2lo @42496
//  GRU: hhi [128][36] @0, hlo @4608, whhh [192][40] @9216, whhl @16896,
//       gh fp32 [128][196] @24576, wih @49664, sbih @50048, sbhh @50240,
//       swo @50432, sbo @50560, x @50564, xh [128][20] @50820       (..53380)
// ---------------------------------------------------------------------------
__global__ void __launch_bounds__(512, 1) fused_kernel(
    const float* __restrict__ z,
    const float* __restrict__ b1, const float* __restrict__ b2, const float* __restrict__ b3,
    const float* __restrict__ Wih, const float* __restrict__ bih, const float* __restrict__ bhh,
    const float* __restrict__ Wo, const float* __restrict__ bo,
    float* __restrict__ out)
{
    extern __shared__ float sm[];
    unsigned* smu = (unsigned*)sm;

    const int tid = threadIdx.x, lane = tid & 31, wid = tid >> 5;
    const int g = lane >> 2, tg = lane & 3;
    const int wm = wid & 3, wn = wid >> 2;
    const int m0 = blockIdx.x * 128;

    unsigned* h1hi = smu;            // [128][132]
    unsigned* h1lo = smu + 16896;
    float*    zbuf = sm + 33792;     // 2 x [128][20]
    unsigned* w1h  = smu + 38912;    // 2 x [256][12]
    unsigned* w1l  = smu + 45056;

    // ================= GEMM1: h1 = relu(z @ W1^T + b1) =================
    float acc1[2][8][4];
    #pragma unroll
    for (int a = 0; a < 2; a++)
        #pragma unroll
        for (int b = 0; b < 8; b++)
            #pragma unroll
            for (int c = 0; c < 4; c++) acc1[a][b][c] = 0.f;

    auto stage1 = [&](int buf, int kc) {
        const int k0 = kc * 16;
        // z: 128 rows x 16 fp32 (row stride 361 not 16B-aligned -> 4B cp.async)
        {
            int m = tid >> 2, q4 = (tid & 3) * 4;
            int gk = k0 + q4;
            float* dst = zbuf + buf * 2560 + m * 20 + q4;
            const float* src = z + (size_t)(m0 + m) * 361 + gk;
            #pragma unroll
            for (int j = 0; j < 4; j++) {
                if (gk + j < 361) cpa4(dst + j, src + j);
                else              dst[j] = 0.f;
            }
        }
        // W1 chunk: 256 rows x 8 u32, smem stride 12
        {
            int n = tid >> 1, q4 = (tid & 1) * 4;
            const unsigned* sh = g_W1h + kc * 2048 + n * 8 + q4;
            const unsigned* sl = g_W1l + kc * 2048 + n * 8 + q4;
            cpa16(w1h + buf * 3072 + n * 12 + q4, sh);
            cpa16(w1l + buf * 3072 + n * 12 + q4, sl);
        }
    };

    stage1(0, 0); cp_commit();
    for (int kc = 0; kc < NCH1; kc++) {
        if (kc + 1 < NCH1) { stage1((kc + 1) & 1, kc + 1); cp_commit(); cp_wait<1>(); }
        else               { cp_wait<0>(); }
        __syncthreads();
        const float* az = zbuf + (kc & 1) * 2560 + (wm * 32) * 20;
        const unsigned* bh = w1h + (kc & 1) * 3072;
        const unsigned* bl = w1l + (kc & 1) * 3072;
        unsigned Ah[2][4], Al[2][4];
        ldA_f32(az,           20, g, tg, Ah[0], Al[0]);
        ldA_f32(az + 16 * 20, 20, g, tg, Ah[1], Al[1]);
        #pragma unroll
        for (int nt = 0; nt < 8; nt++) {
            const unsigned* pb = bh + (wn * 64 + nt * 8 + g) * 12 + tg;
            const unsigned* pc = bl + (wn * 64 + nt * 8 + g) * 12 + tg;
            unsigned B0 = pb[0], B1 = pb[4], C0 = pc[0], C1 = pc[4];
            mma16(acc1[0][nt], Ah[0], B0, B1);
            mma16(acc1[1][nt], Ah[1], B0, B1);
            mma16(acc1[0][nt], Ah[0], C0, C1);
            mma16(acc1[1][nt], Ah[1], C0, C1);
            mma16(acc1[0][nt], Al[0], B0, B1);
            mma16(acc1[1][nt], Al[1], B0, B1);
        }
        __syncthreads();
    }

    // prefetch W2 chunk 0 (over dead z/W1 region)
    unsigned* w2h = smu + 33792;  // 2 x [128][36]
    unsigned* w2l = smu + 43008;
    auto stage2 = [&](int buf, int kc) {
        #pragma unroll
        for (int i = tid; i < 1024; i += 512) {
            int n = i >> 3, q4 = (i & 7) * 4;
            cpa16(w2h + buf * 4608 + n * 36 + q4, g_W2h + kc * 4096 + n * 32 + q4);
            cpa16(w2l + buf * 4608 + n * 36 + q4, g_W2l + kc * 4096 + n * 32 + q4);
        }
    };
    stage2(0, 0); cp_commit();

    // GEMM1 epilogue: h1 = relu(acc + b1) -> packed bf16 hi/lo
    #pragma unroll
    for (int mt = 0; mt < 2; mt++) {
        #pragma unroll
        for (int nt = 0; nt < 8; nt++) {
            int m = wm * 32 + mt * 16 + g;
            int n = wn * 64 + nt * 8 + 2 * tg;
            int nu = n >> 1;
            float bv0 = __ldg(b1 + n), bv1 = __ldg(b1 + n + 1);
            unsigned hi, lo;
            split2(relu_(acc1[mt][nt][0] + bv0), relu_(acc1[mt][nt][1] + bv1), hi, lo);
            h1hi[m * 132 + nu] = hi; h1lo[m * 132 + nu] = lo;
            split2(relu_(acc1[mt][nt][2] + bv0), relu_(acc1[mt][nt][3] + bv1), hi, lo);
            h1hi[(m + 8) * 132 + nu] = hi; h1lo[(m + 8) * 132 + nu] = lo;
        }
    }
    __syncthreads();

    // ================= GEMM2: h2 = relu(h1 @ W2^T + b2), 4 chunks of 64 ======
    float acc2[2][4][4];
    #pragma unroll
    for (int a = 0; a < 2; a++)
        #pragma unroll
        for (int b = 0; b < 4; b++)
            #pragma unroll
            for (int c = 0; c < 4; c++) acc2[a][b][c] = 0.f;

    for (int kc = 0; kc < 4; kc++) {
        if (kc + 1 < 4) { stage2((kc + 1) & 1, kc + 1); cp_commit(); cp_wait<1>(); }
        else            { cp_wait<0>(); }
        __syncthreads();
        const unsigned* bh = w2h + (kc & 1) * 4608;
        const unsigned* bl = w2l + (kc & 1) * 4608;
        #pragma unroll
        for (int q = 0; q < 4; q++) {
            int u0 = kc * 32 + q * 8;
            unsigned Ah[2][4], Al[2][4];
            #pragma unroll
            for (int mt = 0; mt < 2; mt++) {
                int m = wm * 32 + mt * 16 + g;
                Ah[mt][0] = h1hi[m * 132 + u0 + tg];     Ah[mt][1] = h1hi[(m + 8) * 132 + u0 + tg];
                Ah[mt][2] = h1hi[m * 132 + u0 + tg + 4]; Ah[mt][3] = h1hi[(m + 8) * 132 + u0 + tg + 4];
                Al[mt][0] = h1lo[m * 132 + u0 + tg];     Al[mt][1] = h1lo[(m + 8) * 132 + u0 + tg];
                Al[mt][2] = h1lo[m * 132 + u0 + tg + 4]; Al[mt][3] = h1lo[(m + 8) * 132 + u0 + tg + 4];
            }
            #pragma unroll
            for (int nt = 0; nt < 4; nt++) {
                int nrow = wn * 32 + nt * 8 + g;
                const unsigned* pb = bh + nrow * 36 + q * 8 + tg;
                const unsigned* pc = bl + nrow * 36 + q * 8 + tg;
                unsigned B0 = pb[0], B1 = pb[4], C0 = pc[0], C1 = pc[4];
                mma16(acc2[0][nt], Ah[0], B0, B1);
                mma16(acc2[1][nt], Ah[1], B0, B1);
                mma16(acc2[0][nt], Ah[0], C0, C1);
                mma16(acc2[1][nt], Ah[1], C0, C1);
                mma16(acc2[0][nt], Al[0], B0, B1);
                mma16(acc2[1][nt], Al[1], B0, B1);
            }
        }
        __syncthreads();
    }

    // ---- stage W3 (over dead h1 head) + h2 epilogue ----
    unsigned* w3h = smu;          // [64][68]
    unsigned* w3l = smu + 4352;
    #pragma unroll
    for (int i = tid; i < 2048; i += 512) {
        int half = i >> 10, j = i & 1023;
        int n = j >> 4, q4 = (j & 15) * 4;
        cpa16((half ? w3l : w3h) + n * 68 + q4, (half ? g_W3l : g_W3h) + n * 64 + q4);
    }
    cp_commit();

    unsigned* h2hi = smu + 33792;  // [128][68]
    unsigned* h2lo = smu + 42496;
    #pragma unroll
    for (int mt = 0; mt < 2; mt++) {
        #pragma unroll
        for (int nt = 0; nt < 4; nt++) {
            int m = wm * 32 + mt * 16 + g;
            int n = wn * 32 + nt * 8 + 2 * tg;
            int nu = n >> 1;
            float bv0 = __ldg(b2 + n), bv1 = __ldg(b2 + n + 1);
            unsigned hi, lo;
            split2(relu_(acc2[mt][nt][0] + bv0), relu_(acc2[mt][nt][1] + bv1), hi, lo);
            h2hi[m * 68 + nu] = hi; h2lo[m * 68 + nu] = lo;
            split2(relu_(acc2[mt][nt][2] + bv0), relu_(acc2[mt][nt][3] + bv1), hi, lo);
            h2hi[(m + 8) * 68 + nu] = hi; h2lo[(m + 8) * 68 + nu] = lo;
        }
    }
    cp_wait<0>();
    __syncthreads();

    // ================= GEMM3: h = relu(h2 @ W3^T + b3) =================
    float acc3[2][2][4];
    #pragma unroll
    for (int a = 0; a < 2; a++)
        #pragma unroll
        for (int b = 0; b < 2; b++)
            #pragma unroll
            for (int c = 0; c < 4; c++) acc3[a][b][c] = 0.f;

    #pragma unroll
    for (int q = 0; q < 8; q++) {
        int u0 = q * 8;
        unsigned Ah[2][4], Al[2][4];
        #pragma unroll
        for (int mt = 0; mt < 2; mt++) {
            int m = wm * 32 + mt * 16 + g;
            Ah[mt][0] = h2hi[m * 68 + u0 + tg];     Ah[mt][1] = h2hi[(m + 8) * 68 + u0 + tg];
            Ah[mt][2] = h2hi[m * 68 + u0 + tg + 4]; Ah[mt][3] = h2hi[(m + 8) * 68 + u0 + tg + 4];
            Al[mt][0] = h2lo[m * 68 + u0 + tg];     Al[mt][1] = h2lo[(m + 8) * 68 + u0 + tg];
            Al[mt][2] = h2lo[m * 68 + u0 + tg + 4]; Al[mt][3] = h2lo[(m + 8) * 68 + u0 + tg + 4];
        }
        #pragma unroll
        for (int nt = 0; nt < 2; nt++) {
            int nrow = wn * 16 + nt * 8 + g;
            const unsigned* pb = w3h + nrow * 68 + u0 + tg;
            const unsigned* pc = w3l + nrow * 68 + u0 + tg;
            unsigned B0 = pb[0], B1 = pb[4], C0 = pc[0], C1 = pc[4];
            mma16(acc3[0][nt], Ah[0], B0, B1);
            mma16(acc3[1][nt], Ah[1], B0, B1);
            mma16(acc3[0][nt], Ah[0], C0, C1);
            mma16(acc3[1][nt], Ah[1], C0, C1);
            mma16(acc3[0][nt], Al[0], B0, B1);
            mma16(acc3[1][nt], Al[1], B0, B1);
        }
    }
    __syncthreads();   // all w3/h2 reads done before overwrite

    // ================= GRU setup =================
    unsigned* hhi  = smu;            // [128][36]
    unsigned* hlo  = smu + 4608;
    unsigned* whhh = smu + 9216;     // [192][40] permuted pairs
    unsigned* whhl = smu + 16896;
    float*    gh   = sm + 24576;     // [128][196]
    float*    wih  = sm + 49664;     // [192][2]
    float*    sbih = sm + 50048;
    float*    sbhh = sm + 50240;
    float*    swo  = sm + 50432;
    float*    sbo  = sm + 50560;
    float*    x    = sm + 50564;     // [128][2]
    float*    xh   = sm + 50820;     // [128][20]

    #pragma unroll
    for (int i = tid; i < 3072; i += 512) {
        int half = (i >= 1536), j = half ? i - 1536 : i;
        int n = j >> 3, q4 = (j & 7) * 4;
        cpa16((half ? whhl : whhh) + n * 40 + q4, (half ? g_Whl : g_Whh) + n * 32 + q4);
    }
    cp_commit();
    if (tid < 384) wih[tid] = Wih[tid];
    if (tid < 192) { sbih[tid] = bih[tid]; sbhh[tid] = bhh[tid]; }
    if (tid < 128) swo[tid] = Wo[tid];
    if (tid < 2)   sbo[tid] = bo[tid];
    if (tid < 256) x[tid] = 0.f;

    // GEMM3 epilogue -> packed h
    #pragma unroll
    for (int mt = 0; mt < 2; mt++) {
        #pragma unroll
        for (int nt = 0; nt < 2; nt++) {
            int m = wm * 32 + mt * 16 + g;
            int n = wn * 16 + nt * 8 + 2 * tg;
            int nu = n >> 1;
            float bv0 = __ldg(b3 + n), bv1 = __ldg(b3 + n + 1);
            unsigned hi, lo;
            split2(relu_(acc3[mt][nt][0] + bv0), relu_(acc3[mt][nt][1] + bv1), hi, lo);
            hhi[m * 36 + nu] = hi; hlo[m * 36 + nu] = lo;
            split2(relu_(acc3[mt][nt][2] + bv0), relu_(acc3[mt][nt][3] + bv1), hi, lo);
            hhi[(m + 8) * 36 + nu] = hi; hlo[(m + 8) * 36 + nu] = lo;
        }
    }
    cp_wait<0>();
    __syncthreads();

    // ================= GRU loop: serial phases, 2 syncs/step =================
    const int gr = tid >> 2;           // gate row (4 threads per row)
    const int gc = tid & 3;            // gate col quarter
    for (int t = 0; t < PLEN; t++) {
        // ---- gh = h @ Whh^T : all 16 warps, 2mt x 6nt ----
        float acc[2][6][4];
        #pragma unroll
        for (int a = 0; a < 2; a++)
            #pragma unroll
            for (int b = 0; b < 6; b++)
                #pragma unroll
                for (int c = 0; c < 4; c++) acc[a][b][c] = 0.f;

        #pragma unroll
        for (int q = 0; q < 4; q++) {
            int u0 = q * 8;
            unsigned Ah[2][4], Al[2][4];
            #pragma unroll
            for (int mt = 0; mt < 2; mt++) {
                int m = wm * 32 + mt * 16 + g;
                Ah[mt][0] = hhi[m * 36 + u0 + tg];     Ah[mt][1] = hhi[(m + 8) * 36 + u0 + tg];
                Ah[mt][2] = hhi[m * 36 + u0 + tg + 4]; Ah[mt][3] = hhi[(m + 8) * 36 + u0 + tg + 4];
                Al[mt][0] = hlo[m * 36 + u0 + tg];     Al[mt][1] = hlo[(m + 8) * 36 + u0 + tg];
                Al[mt][2] = hlo[m * 36 + u0 + tg + 4]; Al[mt][3] = hlo[(m + 8) * 36 + u0 + tg + 4];
            }
            #pragma unroll
            for (int nt = 0; nt < 6; nt++) {
                int nrow = wn * 48 + nt * 8 + g;
                uint2 B = *(const uint2*)(whhh + nrow * 40 + u0 + tg * 2);
                uint2 C = *(const uint2*)(whhl + nrow * 40 + u0 + tg * 2);
                mma16(acc[0][nt], Ah[0], B.x, B.y);
                mma16(acc[1][nt], Ah[1], B.x, B.y);
                mma16(acc[0][nt], Ah[0], C.x, C.y);
                mma16(acc[1][nt], Ah[1], C.x, C.y);
                mma16(acc[0][nt], Al[0], B.x, B.y);
                mma16(acc[1][nt], Al[1], B.x, B.y);
            }
        }
        #pragma unroll
        for (int mt = 0; mt < 2; mt++) {
            #pragma unroll
            for (int nt = 0; nt < 6; nt++) {
                int m = wm * 32 + mt * 16 + g;
                int n = wn * 48 + nt * 8 + 2 * tg;
                *(float2*)&gh[m * 196 + n]       = make_float2(acc[mt][nt][0], acc[mt][nt][1]);
                *(float2*)&gh[(m + 8) * 196 + n] = make_float2(acc[mt][nt][2], acc[mt][nt][3]);
            }
        }
        __syncthreads();

        // ---- gates (exact fp32, row-mapped) + fused Wo/dx ----
        {
            float x0v = x[2 * gr], x1v = x[2 * gr + 1];
            float s0 = 0.f, s1 = 0.f;
            #pragma unroll
            for (int i = 0; i < 8; i++) {
                int cc = gc * 8 + i;
                unsigned uh = hhi[gr * 36 + cc], ul = hlo[gr * 36 + cc];
                float hv0 = bflo(uh) + bflo(ul);
                float hv1 = bfhi(uh) + bfhi(ul);
                float hn[2];
                #pragma unroll
                for (int e = 0; e < 2; e++) {
                    int j = 2 * cc + e;
                    float ghr = gh[gr * 196 + j]       + sbhh[j];
                    float ghz = gh[gr * 196 + j + 64]  + sbhh[j + 64];
                    float ghn = gh[gr * 196 + j + 128] + sbhh[j + 128];
                    float gir = x0v * wih[j * 2]         + x1v * wih[j * 2 + 1]         + sbih[j];
                    float giz = x0v * wih[(j + 64) * 2]  + x1v * wih[(j + 64) * 2 + 1]  + sbih[j + 64];
                    float gin = x0v * wih[(j + 128) * 2] + x1v * wih[(j + 128) * 2 + 1] + sbih[j + 128];
                    float rg = __fdividef(1.f, 1.f + __expf(-(gir + ghr)));
                    float zg = __fdividef(1.f, 1.f + __expf(-(giz + ghz)));
                    float av = gin + rg * ghn;
                    float e2 = __expf(2.f * fabsf(av));
                    float tv = 1.f - __fdividef(2.f, e2 + 1.f);
                    float ng = copysignf(tv, av);
                    float hv = e ? hv1 : hv0;
                    hn[e] = (1.f - zg) * ng + zg * hv;
                }
                unsigned nhi, nlo;
                split2(hn[0], hn[1], nhi, nlo);
                hhi[gr * 36 + cc] = nhi; hlo[gr * 36 + cc] = nlo;
                s0 += hn[0] * swo[2 * cc]      + hn[1] * swo[2 * cc + 1];
                s1 += hn[0] * swo[64 + 2 * cc] + hn[1] * swo[64 + 2 * cc + 1];
            }
            s0 += __shfl_xor_sync(0xFFFFFFFFu, s0, 1);
            s0 += __shfl_xor_sync(0xFFFFFFFFu, s0, 2);
            s1 += __shfl_xor_sync(0xFFFFFFFFu, s1, 1);
            s1 += __shfl_xor_sync(0xFFFFFFFFu, s1, 2);
            if (gc == 0) {
                float xv0 = x0v + s0 + sbo[0];
                float xv1 = x1v + s1 + sbo[1];
                x[2 * gr] = xv0; x[2 * gr + 1] = xv1;
                xh[gr * 20 + 2 * t] = xv0; xh[gr * 20 + 2 * t + 1] = xv1;
            }
        }
        __syncthreads();
    }

    // coalesced output: out[b, t, o]
    #pragma unroll
    for (int i = tid; i < 640; i += 512) {
        int r = i / 5, q = (i % 5) * 4;
        *(float4*)&out[(size_t)(m0 + r) * 20 + q] = *(const float4*)&xh[r * 20 + q];
    }
}

// ---------------------------------------------------------------------------
extern "C" void kernel_launch(void* const* d_in, const int* in_sizes, int n_in,
                              void* d_out, int out_size)
{
    const float* z   = (const float*)d_in[0];
    const float* W1  = (const float*)d_in[1];
    const float* b1  = (const float*)d_in[2];
    const float* W2  = (const float*)d_in[3];
    const float* b2  = (const float*)d_in[4];
    const float* W3  = (const float*)d_in[5];
    const float* b3  = (const float*)d_in[6];
    const float* Wih = (const float*)d_in[7];
    const float* Whh = (const float*)d_in[8];
    const float* bih = (const float*)d_in[9];
    const float* bhh = (const float*)d_in[10];
    const float* Wo  = (const float*)d_in[11];
    const float* bo  = (const float*)d_in[12];
    float* out = (float*)d_out;

    const int smem = 53380 * 4;  // 213520 B
    cudaFuncSetAttribute(fused_kernel, cudaFuncAttributeMaxDynamicSharedMemorySize, smem);

    prep_kernel<<<288, 256>>>(W1, W2, W3, Whh);
    fused_kernel<<<BS / 128, 512, smem>>>(z, b1, b2, b3, Wih, bih, bhh, Wo, bo, out);
}

// round 11
// speedup vs baseline: 1.3419x; 1.3419x over previous
#include <cuda_runtime.h>
#include <cuda_bf16.h>

#define BS 131072
#define PLEN 10
#define NCH1 23   // GEMM1: K=361 padded to 368 = 23 chunks of 16

// -------- pre-split weights: packed bf16 (2 per u32 along k), hi & lo, natural order
__device__ __align__(16) unsigned g_W1h[NCH1 * 256 * 8], g_W1l[NCH1 * 256 * 8]; // [kc][n][8]
__device__ __align__(16) unsigned g_W2h[4 * 128 * 32],   g_W2l[4 * 128 * 32];   // [kc][n][32]
__device__ __align__(16) unsigned g_W3h[64 * 64],        g_W3l[64 * 64];        // [n][64]
__device__ __align__(16) unsigned g_Whh[192 * 32],       g_Whl[192 * 32];       // [n][32]

// ---------------------------------------------------------------------------
__device__ __forceinline__ unsigned packbf(float lo, float hi) {
    unsigned r;
    asm("cvt.rn.bf16x2.f32 %0, %1, %2;" : "=r"(r) : "f"(hi), "f"(lo));
    return r;
}
__device__ __forceinline__ void split2(float v0, float v1, unsigned& hi, unsigned& lo) {
    hi = packbf(v0, v1);
    float h0 = __uint_as_float(hi << 16);
    float h1 = __uint_as_float(hi & 0xffff0000u);
    lo = packbf(v0 - h0, v1 - h1);
}
__device__ __forceinline__ float relu_(float v) { return v > 0.f ? v : 0.f; }

__device__ __forceinline__ void mma16(float* c, const unsigned* a, unsigned b0, unsigned b1) {
    asm("mma.sync.aligned.m16n8k16.row.col.f32.bf16.bf16.f32 "
        "{%0,%1,%2,%3},{%4,%5,%6,%7},{%8,%9},{%0,%1,%2,%3};"
        : "+f"(c[0]), "+f"(c[1]), "+f"(c[2]), "+f"(c[3])
        : "r"(a[0]), "r"(a[1]), "r"(a[2]), "r"(a[3]), "r"(b0), "r"(b1));
}

// ldmatrix x4: one instruction = 4 fragment regs
__device__ __forceinline__ void ldsm4(unsigned& r0, unsigned& r1, unsigned& r2, unsigned& r3,
                                      unsigned addr) {
    asm volatile("ldmatrix.sync.aligned.m8n8.x4.shared.b16 {%0,%1,%2,%3}, [%4];"
        : "=r"(r0), "=r"(r1), "=r"(r2), "=r"(r3) : "r"(addr));
}

__device__ __forceinline__ void cpa4(void* s, const void* g) {
    unsigned a = (unsigned)__cvta_generic_to_shared(s);
    asm volatile("cp.async.ca.shared.global [%0],[%1],4;" :: "r"(a), "l"(g) : "memory");
}
__device__ __forceinline__ void cpa16(void* s, const void* g) {
    unsigned a = (unsigned)__cvta_generic_to_shared(s);
    asm volatile("cp.async.cg.shared.global [%0],[%1],16;" :: "r"(a), "l"(g) : "memory");
}
__device__ __forceinline__ void cp_commit() { asm volatile("cp.async.commit_group;" ::: "memory"); }
template <int N>
__device__ __forceinline__ void cp_wait() { asm volatile("cp.async.wait_group %0;" :: "n"(N) : "memory"); }

// load fp32 A tile fragment (16 rows) and split to bf16 hi/lo frags
__device__ __forceinline__ void ldA_f32(const float* base, int stride, int g, int tg,
                                        unsigned* Ah, unsigned* Al) {
    float2 p0 = *(const float2*)(base + g * stride + 2 * tg);
    float2 p1 = *(const float2*)(base + (g + 8) * stride + 2 * tg);
    float2 p2 = *(const float2*)(base + g * stride + 2 * tg + 8);
    float2 p3 = *(const float2*)(base + (g + 8) * stride + 2 * tg + 8);
    split2(p0.x, p0.y, Ah[0], Al[0]);
    split2(p1.x, p1.y, Ah[1], Al[1]);
    split2(p2.x, p2.y, Ah[2], Al[2]);
    split2(p3.x, p3.y, Ah[3], Al[3]);
}

// ---------------------------------------------------------------------------
// prep kernel: fp32 weights -> packed bf16 hi/lo global scratch (natural order)
// ---------------------------------------------------------------------------
__global__ void prep_kernel(const float* __restrict__ W1, const float* __restrict__ W2,
                            const float* __restrict__ W3, const float* __restrict__ Whh) {
    int i = blockIdx.x * 256 + threadIdx.x;
    const int N1 = NCH1 * 256 * 8, N2 = 4 * 128 * 32, N3 = 64 * 64, N4 = 192 * 32;
    if (i < N1) {
        int kc = i >> 11, rem = i & 2047, n = rem >> 3, u = rem & 7;
        int k = kc * 16 + 2 * u;
        float v0 = (k < 361)     ? W1[n * 361 + k]     : 0.f;
        float v1 = (k + 1 < 361) ? W1[n * 361 + k + 1] : 0.f;
        split2(v0, v1, g_W1h[i], g_W1l[i]);
    } else if (i < N1 + N2) {
        int j = i - N1;
        int kc = j >> 12, rem = j & 4095, n = rem >> 5, u = rem & 31;
        int k = kc * 64 + 2 * u;
        split2(W2[n * 256 + k], W2[n * 256 + k + 1], g_W2h[j], g_W2l[j]);
    } else if (i < N1 + N2 + N3) {
        int j = i - N1 - N2;
        int n = j >> 6, u = j & 63;
        split2(W3[n * 128 + 2 * u], W3[n * 128 + 2 * u + 1], g_W3h[j], g_W3l[j]);
    } else if (i < N1 + N2 + N3 + N4) {
        int j = i - N1 - N2 - N3;
        int n = j >> 5, u = j & 31;
        split2(Whh[n * 64 + 2 * u], Whh[n * 64 + 2 * u + 1], g_Whh[j], g_Whl[j]);
    }
}

// ---------------------------------------------------------------------------
// fused kernel: MLP (3 GEMMs) + GRU. 128 rows/CTA, 512 threads.
// EXACT smem map of the 899us kernel; only fragment loads changed to ldmatrix.
//  h1hi [128][132] @0, h1lo @16896                                 (..33792)
//  P1: zbuf 2x[128][20] @33792, w1h 2x[256][12] @38912, w1l @45056 (..51200)
//  P2: w2h 2x[128][36] @33792, w2l @43008                          (..52224)
//  P3: h fp32 [128][68] @0, w3h [64][68] @8704, w3l @13056,
//      h2hi [128][68] @33792, h2lo @42496
//  GRU: h @0, gh [128][196] @8704, whhh [192][36] @33792, whhl @40704,
//       wih @47616, sbih @48000, sbhh @48192, swo @48384, sbo @48512,
//       x @48516, xh [128][20] @48772
// ---------------------------------------------------------------------------
__global__ void __launch_bounds__(512, 1) fused_kernel(
    const float* __restrict__ z,
    const float* __restrict__ b1, const float* __restrict__ b2, const float* __restrict__ b3,
    const float* __restrict__ Wih, const float* __restrict__ bih, const float* __restrict__ bhh,
    const float* __restrict__ Wo, const float* __restrict__ bo,
    float* __restrict__ out)
{
    extern __shared__ float sm[];
    unsigned* smu = (unsigned*)sm;
    const unsigned sb = (unsigned)__cvta_generic_to_shared(sm);

    const int tid = threadIdx.x, lane = tid & 31, wid = tid >> 5;
    const int g = lane >> 2, tg = lane & 3;
    const int wm = wid & 3, wn = wid >> 2;
    const int m0 = blockIdx.x * 128;

    // ldmatrix lane-derived constants (u32 units)
    const int arow = lane & 15;                    // A x4: row within 16
    const int ak4  = (lane >> 4) * 4;              // A x4: k-half offset
    const int brow = ((lane >> 4) << 3) + (lane & 7); // B x4: row within 16 (2 tiles)
    const int bk4  = ((lane >> 3) & 1) * 4;        // B x4: k-half offset

    unsigned* h1hi = smu;            // [128][132]
    unsigned* h1lo = smu + 16896;
    float*    zbuf = sm + 33792;     // 2 x [128][20]

    // ================= GEMM1: h1 = relu(z @ W1^T + b1) =================
    float acc1[2][8][4];
    #pragma unroll
    for (int a = 0; a < 2; a++)
        #pragma unroll
        for (int b = 0; b < 8; b++)
            #pragma unroll
            for (int c = 0; c < 4; c++) acc1[a][b][c] = 0.f;

    auto stage1 = [&](int buf, int kc) {
        const int k0 = kc * 16;
        {
            int m = tid >> 2, q4 = (tid & 3) * 4;
            int gk = k0 + q4;
            float* dst = zbuf + buf * 2560 + m * 20 + q4;
            const float* src = z + (size_t)(m0 + m) * 361 + gk;
            #pragma unroll
            for (int j = 0; j < 4; j++) {
                if (gk + j < 361) cpa4(dst + j, src + j);
                else              dst[j] = 0.f;
            }
        }
        {
            int n = tid >> 1, q4 = (tid & 1) * 4;
            cpa16(smu + 38912 + buf * 3072 + n * 12 + q4, g_W1h + kc * 2048 + n * 8 + q4);
            cpa16(smu + 45056 + buf * 3072 + n * 12 + q4, g_W1l + kc * 2048 + n * 8 + q4);
        }
    };

    // per-warp ldmatrix base offsets (u32) for W1 (stride 12)
    const int w1_frag = (wn * 64 + brow) * 12 + bk4;

    stage1(0, 0); cp_commit();
    for (int kc = 0; kc < NCH1; kc++) {
        if (kc + 1 < NCH1) { stage1((kc + 1) & 1, kc + 1); cp_commit(); cp_wait<1>(); }
        else               { cp_wait<0>(); }
        __syncthreads();
        const float* az = zbuf + (kc & 1) * 2560 + (wm * 32) * 20;
        unsigned bh_addr = sb + 4u * (38912 + (kc & 1) * 3072 + w1_frag);
        unsigned bl_addr = bh_addr + 4u * 6144;
        unsigned Ah[2][4], Al[2][4];
        ldA_f32(az,           20, g, tg, Ah[0], Al[0]);
        ldA_f32(az + 16 * 20, 20, g, tg, Ah[1], Al[1]);
        #pragma unroll
        for (int p = 0; p < 4; p++) {
            unsigned bh[4], bl[4];
            ldsm4(bh[0], bh[1], bh[2], bh[3], bh_addr + 4u * (p * 16 * 12));
            ldsm4(bl[0], bl[1], bl[2], bl[3], bl_addr + 4u * (p * 16 * 12));
            mma16(acc1[0][2*p],   Ah[0], bh[0], bh[1]);
            mma16(acc1[1][2*p],   Ah[1], bh[0], bh[1]);
            mma16(acc1[0][2*p],   Ah[0], bl[0], bl[1]);
            mma16(acc1[1][2*p],   Ah[1], bl[0], bl[1]);
            mma16(acc1[0][2*p],   Al[0], bh[0], bh[1]);
            mma16(acc1[1][2*p],   Al[1], bh[0], bh[1]);
            mma16(acc1[0][2*p+1], Ah[0], bh[2], bh[3]);
            mma16(acc1[1][2*p+1], Ah[1], bh[2], bh[3]);
            mma16(acc1[0][2*p+1], Ah[0], bl[2], bl[3]);
            mma16(acc1[1][2*p+1], Ah[1], bl[2], bl[3]);
            mma16(acc1[0][2*p+1], Al[0], bh[2], bh[3]);
            mma16(acc1[1][2*p+1], Al[1], bh[2], bh[3]);
        }
        __syncthreads();
    }

    // prefetch W2 chunk 0 (over dead z/W1 region)
    auto stage2 = [&](int buf, int kc) {
        #pragma unroll
        for (int i = tid; i < 1024; i += 512) {
            int n = i >> 3, q4 = (i & 7) * 4;
            cpa16(smu + 33792 + buf * 4608 + n * 36 + q4, g_W2h + kc * 4096 + n * 32 + q4);
            cpa16(smu + 43008 + buf * 4608 + n * 36 + q4, g_W2l + kc * 4096 + n * 32 + q4);
        }
    };
    stage2(0, 0); cp_commit();

    // GEMM1 epilogue: h1 = relu(acc + b1) -> packed bf16 hi/lo
    #pragma unroll
    for (int mt = 0; mt < 2; mt++) {
        #pragma unroll
        for (int nt = 0; nt < 8; nt++) {
            int m = wm * 32 + mt * 16 + g;
            int n = wn * 64 + nt * 8 + 2 * tg;
            int nu = n >> 1;
            float bv0 = __ldg(b1 + n), bv1 = __ldg(b1 + n + 1);
            unsigned hi, lo;
            split2(relu_(acc1[mt][nt][0] + bv0), relu_(acc1[mt][nt][1] + bv1), hi, lo);
            h1hi[m * 132 + nu] = hi; h1lo[m * 132 + nu] = lo;
            split2(relu_(acc1[mt][nt][2] + bv0), relu_(acc1[mt][nt][3] + bv1), hi, lo);
            h1hi[(m + 8) * 132 + nu] = hi; h1lo[(m + 8) * 132 + nu] = lo;
        }
    }
    __syncthreads();

    // ================= GEMM2: h2 = relu(h1 @ W2^T + b2), 4 chunks of 64 ======
    float acc2[2][4][4];
    #pragma unroll
    for (int a = 0; a < 2; a++)
        #pragma unroll
        for (int b = 0; b < 4; b++)
            #pragma unroll
            for (int c = 0; c < 4; c++) acc2[a][b][c] = 0.f;

    const int h1_fragA = (wm * 32 + arow) * 132 + ak4;   // stride 132
    const int w2_fragB = (wn * 32 + brow) * 36 + bk4;    // stride 36

    for (int kc = 0; kc < 4; kc++) {
        if (kc + 1 < 4) { stage2((kc + 1) & 1, kc + 1); cp_commit(); cp_wait<1>(); }
        else            { cp_wait<0>(); }
        __syncthreads();
        unsigned w2h_addr = sb + 4u * (33792 + (kc & 1) * 4608 + w2_fragB);
        unsigned w2l_addr = w2h_addr + 4u * 9216;
        #pragma unroll
        for (int q = 0; q < 4; q++) {
            int u0 = kc * 32 + q * 8;
            unsigned Ah[2][4], Al[2][4];
            ldsm4(Ah[0][0], Ah[0][1], Ah[0][2], Ah[0][3], sb + 4u * (h1_fragA + u0));
            ldsm4(Ah[1][0], Ah[1][1], Ah[1][2], Ah[1][3], sb + 4u * (h1_fragA + 16 * 132 + u0));
            ldsm4(Al[0][0], Al[0][1], Al[0][2], Al[0][3], sb + 4u * (16896 + h1_fragA + u0));
            ldsm4(Al[1][0], Al[1][1], Al[1][2], Al[1][3], sb + 4u * (16896 + h1_fragA + 16 * 132 + u0));
            #pragma unroll
            for (int p = 0; p < 2; p++) {
                unsigned bh[4], bl[4];
                ldsm4(bh[0], bh[1], bh[2], bh[3], w2h_addr + 4u * (p * 16 * 36 + q * 8));
                ldsm4(bl[0], bl[1], bl[2], bl[3], w2l_addr + 4u * (p * 16 * 36 + q * 8));
                mma16(acc2[0][2*p],   Ah[0], bh[0], bh[1]);
                mma16(acc2[1][2*p],   Ah[1], bh[0], bh[1]);
                mma16(acc2[0][2*p],   Ah[0], bl[0], bl[1]);
                mma16(acc2[1][2*p],   Ah[1], bl[0], bl[1]);
                mma16(acc2[0][2*p],   Al[0], bh[0], bh[1]);
                mma16(acc2[1][2*p],   Al[1], bh[0], bh[1]);
                mma16(acc2[0][2*p+1], Ah[0], bh[2], bh[3]);
                mma16(acc2[1][2*p+1], Ah[1], bh[2], bh[3]);
                mma16(acc2[0][2*p+1], Ah[0], bl[2], bl[3]);
                mma16(acc2[1][2*p+1], Ah[1], bl[2], bl[3]);
                mma16(acc2[0][2*p+1], Al[0], bh[2], bh[3]);
                mma16(acc2[1][2*p+1], Al[1], bh[2], bh[3]);
            }
        }
        __syncthreads();
    }

    // ---- stage W3 @8704/13056 (over dead h1 rows) + h2 epilogue @33792 ----
    unsigned* w3h = smu + 8704;   // [64][68]
    unsigned* w3l = smu + 13056;
    #pragma unroll
    for (int i = tid; i < 2048; i += 512) {
        int half = i >> 10, j = i & 1023;
        int n = j >> 4, q4 = (j & 15) * 4;
        cpa16((half ? w3l : w3h) + n * 68 + q4, (half ? g_W3l : g_W3h) + n * 64 + q4);
    }
    cp_commit();

    unsigned* h2hi = smu + 33792;  // [128][68]
    unsigned* h2lo = smu + 42496;
    #pragma unroll
    for (int mt = 0; mt < 2; mt++) {
        #pragma unroll
        for (int nt = 0; nt < 4; nt++) {
            int m = wm * 32 + mt * 16 + g;
            int n = wn * 32 + nt * 8 + 2 * tg;
            int nu = n >> 1;
            float bv0 = __ldg(b2 + n), bv1 = __ldg(b2 + n + 1);
            unsigned hi, lo;
            split2(relu_(acc2[mt][nt][0] + bv0), relu_(acc2[mt][nt][1] + bv1), hi, lo);
            h2hi[m * 68 + nu] = hi; h2lo[m * 68 + nu] = lo;
            split2(relu_(acc2[mt][nt][2] + bv0), relu_(acc2[mt][nt][3] + bv1), hi, lo);
            h2hi[(m + 8) * 68 + nu] = hi; h2lo[(m + 8) * 68 + nu] = lo;
        }
    }
    cp_wait<0>();
    __syncthreads();

    // ================= GEMM3: h = relu(h2 @ W3^T + b3) =================
    float acc3[2][2][4];
    #pragma unroll
    for (int a = 0; a < 2; a++)
        #pragma unroll
        for (int b = 0; b < 2; b++)
            #pragma unroll
            for (int c = 0; c < 4; c++) acc3[a][b][c] = 0.f;

    const int h2_fragA = 33792 + (wm * 32 + arow) * 68 + ak4;   // stride 68
    const int w3_fragB = 8704 + (wn * 16 + brow) * 68 + bk4;    // stride 68

    #pragma unroll
    for (int q = 0; q < 8; q++) {
        int u0 = q * 8;
        unsigned Ah[2][4], Al[2][4];
        ldsm4(Ah[0][0], Ah[0][1], Ah[0][2], Ah[0][3], sb + 4u * (h2_fragA + u0));
        ldsm4(Ah[1][0], Ah[1][1], Ah[1][2], Ah[1][3], sb + 4u * (h2_fragA + 16 * 68 + u0));
        ldsm4(Al[0][0], Al[0][1], Al[0][2], Al[0][3], sb + 4u * (8704 + h2_fragA + u0));
        ldsm4(Al[1][0], Al[1][1], Al[1][2], Al[1][3], sb + 4u * (8704 + h2_fragA + 16 * 68 + u0));
        unsigned bh[4], bl[4];
        ldsm4(bh[0], bh[1], bh[2], bh[3], sb + 4u * (w3_fragB + u0));
        ldsm4(bl[0], bl[1], bl[2], bl[3], sb + 4u * (4352 + w3_fragB + u0));
        mma16(acc3[0][0], Ah[0], bh[0], bh[1]);
        mma16(acc3[1][0], Ah[1], bh[0], bh[1]);
        mma16(acc3[0][0], Ah[0], bl[0], bl[1]);
        mma16(acc3[1][0], Ah[1], bl[0], bl[1]);
        mma16(acc3[0][0], Al[0], bh[0], bh[1]);
        mma16(acc3[1][0], Al[1], bh[0], bh[1]);
        mma16(acc3[0][1], Ah[0], bh[2], bh[3]);
        mma16(acc3[1][1], Ah[1], bh[2], bh[3]);
        mma16(acc3[0][1], Ah[0], bl[2], bl[3]);
        mma16(acc3[1][1], Ah[1], bl[2], bl[3]);
        mma16(acc3[0][1], Al[0], bh[2], bh[3]);
        mma16(acc3[1][1], Al[1], bh[2], bh[3]);
    }
    __syncthreads();   // all w3/h2 reads done before overwrite

    // ================= GRU setup =================
    float*    h     = sm;                // [128][68] fp32
    float*    gh    = sm + 8704;         // [128][196]
    unsigned* whhh  = smu + 33792;       // [192][36]
    unsigned* whhl  = smu + 40704;
    float*    wih   = sm + 47616;        // [192][2]
    float*    sbih  = sm + 48000;
    float*    sbhh  = sm + 48192;
    float*    swo   = sm + 48384;
    float*    sbo   = sm + 48512;
    float*    x     = sm + 48516;        // [128][2]
    float*    xh    = sm + 48772;        // [128][20]

    #pragma unroll
    for (int i = tid; i < 3072; i += 512) {
        int half = (i >= 1536), j = half ? i - 1536 : i;
        int n = j >> 3, q4 = (j & 7) * 4;
        cpa16((half ? whhl : whhh) + n * 36 + q4, (half ? g_Whl : g_Whh) + n * 32 + q4);
    }
    cp_commit();
    if (tid < 384) wih[tid] = Wih[tid];
    if (tid < 192) { sbih[tid] = bih[tid]; sbhh[tid] = bhh[tid]; }
    if (tid < 128) swo[tid] = Wo[tid];
    if (tid < 2)   sbo[tid] = bo[tid];
    if (tid < 256) x[tid] = 0.f;

    // GEMM3 epilogue: h = relu(acc + b3) fp32 @0
    #pragma unroll
    for (int mt = 0; mt < 2; mt++) {
        #pragma unroll
        for (int nt = 0; nt < 2; nt++) {
            int m = wm * 32 + mt * 16 + g;
            int n = wn * 16 + nt * 8 + 2 * tg;
            float bv0 = __ldg(b3 + n), bv1 = __ldg(b3 + n + 1);
            h[m * 68 + n]           = relu_(acc3[mt][nt][0] + bv0);
            h[m * 68 + n + 1]       = relu_(acc3[mt][nt][1] + bv1);
            h[(m + 8) * 68 + n]     = relu_(acc3[mt][nt][2] + bv0);
            h[(m + 8) * 68 + n + 1] = relu_(acc3[mt][nt][3] + bv1);
        }
    }
    cp_wait<0>();
    __syncthreads();

    // ================= GRU loop (899us structure; B loads via ldmatrix) ======
    const int whh_fragB = 33792 + (wn * 48 + brow) * 36 + bk4;  // stride 36
    for (int t = 0; t < PLEN; t++) {
        float acc[2][6][4];
        #pragma unroll
        for (int a = 0; a < 2; a++)
            #pragma unroll
            for (int b = 0; b < 6; b++)
                #pragma unroll
                for (int c = 0; c < 4; c++) acc[a][b][c] = 0.f;

        #pragma unroll
        for (int q = 0; q < 4; q++) {
            unsigned Ah[2][4], Al[2][4];
            ldA_f32(h + (wm * 32) * 68 + q * 16,      68, g, tg, Ah[0], Al[0]);
            ldA_f32(h + (wm * 32 + 16) * 68 + q * 16, 68, g, tg, Ah[1], Al[1]);
            #pragma unroll
            for (int p = 0; p < 3; p++) {
                unsigned bh[4], bl[4];
                ldsm4(bh[0], bh[1], bh[2], bh[3], sb + 4u * (whh_fragB + p * 16 * 36 + q * 8));
                ldsm4(bl[0], bl[1], bl[2], bl[3], sb + 4u * (6912 + whh_fragB + p * 16 * 36 + q * 8));
                mma16(acc[0][2*p],   Ah[0], bh[0], bh[1]);
                mma16(acc[1][2*p],   Ah[1], bh[0], bh[1]);
                mma16(acc[0][2*p],   Ah[0], bl[0], bl[1]);
                mma16(acc[1][2*p],   Ah[1], bl[0], bl[1]);
                mma16(acc[0][2*p],   Al[0], bh[0], bh[1]);
                mma16(acc[1][2*p],   Al[1], bh[0], bh[1]);
                mma16(acc[0][2*p+1], Ah[0], bh[2], bh[3]);
                mma16(acc[1][2*p+1], Ah[1], bh[2], bh[3]);
                mma16(acc[0][2*p+1], Ah[0], bl[2], bl[3]);
                mma16(acc[1][2*p+1], Ah[1], bl[2], bl[3]);
                mma16(acc[0][2*p+1], Al[0], bh[2], bh[3]);
                mma16(acc[1][2*p+1], Al[1], bh[2], bh[3]);
            }
        }
        #pragma unroll
        for (int mt = 0; mt < 2; mt++) {
            #pragma unroll
            for (int nt = 0; nt < 6; nt++) {
                int m = wm * 32 + mt * 16 + g;
                int n = wn * 48 + nt * 8 + 2 * tg;
                *(float2*)&gh[m * 196 + n]       = make_float2(acc[mt][nt][0], acc[mt][nt][1]);
                *(float2*)&gh[(m + 8) * 196 + n] = make_float2(acc[mt][nt][2], acc[mt][nt][3]);
            }
        }
        __syncthreads();

        // gates (exact fp32), in-place h update
        #pragma unroll
        for (int e = tid; e < 8192; e += 512) {
            int r = e >> 6, j = e & 63;
            float x0v = x[r * 2], x1v = x[r * 2 + 1];
            float ghr = gh[r * 196 + j]       + sbhh[j];
            float ghz = gh[r * 196 + j + 64]  + sbhh[j + 64];
            float ghn = gh[r * 196 + j + 128] + sbhh[j + 128];
            float gir = x0v * wih[j * 2]           + x1v * wih[j * 2 + 1]           + sbih[j];
            float giz = x0v * wih[(j + 64) * 2]    + x1v * wih[(j + 64) * 2 + 1]    + sbih[j + 64];
            float gin = x0v * wih[(j + 128) * 2]   + x1v * wih[(j + 128) * 2 + 1]   + sbih[j + 128];
            float rg = __fdividef(1.f, 1.f + __expf(-(gir + ghr)));
            float zg = __fdividef(1.f, 1.f + __expf(-(giz + ghz)));
            float av = gin + rg * ghn;
            float e2 = __expf(2.f * fabsf(av));
            float tv = 1.f - __fdividef(2.f, e2 + 1.f);
            float ng = copysignf(tv, av);
            float hv = h[r * 68 + j];
            h[r * 68 + j] = (1.f - zg) * ng + zg * hv;
        }
        __syncthreads();

        // dx = h_new @ Wo^T + bo ; x += dx
        if (tid < 256) {
            int r = tid >> 1, o = tid & 1;
            float s = sbo[o];
            const float* hr = h + r * 68;
            const float* wr = swo + o * 64;
            #pragma unroll 8
            for (int j = 0; j < 64; j++) s += hr[j] * wr[j];
            float xv = x[r * 2 + o] + s;
            x[r * 2 + o] = xv;
            xh[r * 20 + t * 2 + o] = xv;
        }
        __syncthreads();
    }

    // coalesced output: out[b, t, o]
    #pragma unroll
    for (int i = tid; i < 640; i += 512) {
        int r = i / 5, q = (i % 5) * 4;
        *(float4*)&out[(size_t)(m0 + r) * 20 + q] = *(const float4*)&xh[r * 20 + q];
    }
}

// ---------------------------------------------------------------------------
extern "C" void kernel_launch(void* const* d_in, const int* in_sizes, int n_in,
                              void* d_out, int out_size)
{
    const float* z   = (const float*)d_in[0];
    const float* W1  = (const float*)d_in[1];
    const float* b1  = (const float*)d_in[2];
    const float* W2  = (const float*)d_in[3];
    const float* b2  = (const float*)d_in[4];
    const float* W3  = (const float*)d_in[5];
    const float* b3  = (const float*)d_in[6];
    const float* Wih = (const float*)d_in[7];
    const float* Whh = (const float*)d_in[8];
    const float* bih = (const float*)d_in[9];
    const float* bhh = (const float*)d_in[10];
    const float* Wo  = (const float*)d_in[11];
    const float* bo  = (const float*)d_in[12];
    float* out = (float*)d_out;

    const int smem = 52224 * 4;  // 208896 B
    cudaFuncSetAttribute(fused_kernel, cudaFuncAttributeMaxDynamicSharedMemorySize, smem);

    prep_kernel<<<288, 256>>>(W1, W2, W3, Whh);
    fused_kernel<<<BS / 128, 512, smem>>>(z, b1, b2, b3, Wih, bih, bhh, Wo, bo, out);
}

// round 12
// speedup vs baseline: 1.4221x; 1.0598x over previous
#include <cuda_runtime.h>
#include <cuda_bf16.h>

#define BS 131072
#define PLEN 10
#define NCH1 23   // GEMM1: K=361 padded to 368 = 23 chunks of 16

// -------- pre-split weights: packed bf16 (2 per u32 along k), hi & lo, natural order
__device__ __align__(16) unsigned g_W1h[NCH1 * 256 * 8], g_W1l[NCH1 * 256 * 8]; // [kc][n][8]
__device__ __align__(16) unsigned g_W2h[4 * 128 * 32],   g_W2l[4 * 128 * 32];   // [kc][n][32]
__device__ __align__(16) unsigned g_W3h[64 * 64],        g_W3l[64 * 64];        // [n][64]
__device__ __align__(16) unsigned g_Whh[192 * 32],       g_Whl[192 * 32];       // [n][32]

// ---------------------------------------------------------------------------
__device__ __forceinline__ unsigned packbf(float lo, float hi) {
    unsigned r;
    asm("cvt.rn.bf16x2.f32 %0, %1, %2;" : "=r"(r) : "f"(hi), "f"(lo));
    return r;
}
__device__ __forceinline__ void split2(float v0, float v1, unsigned& hi, unsigned& lo) {
    hi = packbf(v0, v1);
    float h0 = __uint_as_float(hi << 16);
    float h1 = __uint_as_float(hi & 0xffff0000u);
    lo = packbf(v0 - h0, v1 - h1);
}
__device__ __forceinline__ float relu_(float v) { return v > 0.f ? v : 0.f; }
__device__ __forceinline__ float tanhapx(float x) {
    float y; asm("tanh.approx.f32 %0, %1;" : "=f"(y) : "f"(x)); return y;
}

__device__ __forceinline__ void mma16(float* c, const unsigned* a, unsigned b0, unsigned b1) {
    asm("mma.sync.aligned.m16n8k16.row.col.f32.bf16.bf16.f32 "
        "{%0,%1,%2,%3},{%4,%5,%6,%7},{%8,%9},{%0,%1,%2,%3};"
        : "+f"(c[0]), "+f"(c[1]), "+f"(c[2]), "+f"(c[3])
        : "r"(a[0]), "r"(a[1]), "r"(a[2]), "r"(a[3]), "r"(b0), "r"(b1));
}

// ldmatrix x4: one instruction = 4 fragment regs
__device__ __forceinline__ void ldsm4(unsigned& r0, unsigned& r1, unsigned& r2, unsigned& r3,
                                      unsigned addr) {
    asm volatile("ldmatrix.sync.aligned.m8n8.x4.shared.b16 {%0,%1,%2,%3}, [%4];"
        : "=r"(r0), "=r"(r1), "=r"(r2), "=r"(r3) : "r"(addr));
}

__device__ __forceinline__ void cpa4(void* s, const void* g) {
    unsigned a = (unsigned)__cvta_generic_to_shared(s);
    asm volatile("cp.async.ca.shared.global [%0],[%1],4;" :: "r"(a), "l"(g) : "memory");
}
__device__ __forceinline__ void cpa16(void* s, const void* g) {
    unsigned a = (unsigned)__cvta_generic_to_shared(s);
    asm volatile("cp.async.cg.shared.global [%0],[%1],16;" :: "r"(a), "l"(g) : "memory");
}
__device__ __forceinline__ void cp_commit() { asm volatile("cp.async.commit_group;" ::: "memory"); }
template <int N>
__device__ __forceinline__ void cp_wait() { asm volatile("cp.async.wait_group %0;" :: "n"(N) : "memory"); }

// load fp32 A tile fragment (16 rows) and split to bf16 hi/lo frags
__device__ __forceinline__ void ldA_f32(const float* base, int stride, int g, int tg,
                                        unsigned* Ah, unsigned* Al) {
    float2 p0 = *(const float2*)(base + g * stride + 2 * tg);
    float2 p1 = *(const float2*)(base + (g + 8) * stride + 2 * tg);
    float2 p2 = *(const float2*)(base + g * stride + 2 * tg + 8);
    float2 p3 = *(const float2*)(base + (g + 8) * stride + 2 * tg + 8);
    split2(p0.x, p0.y, Ah[0], Al[0]);
    split2(p1.x, p1.y, Ah[1], Al[1]);
    split2(p2.x, p2.y, Ah[2], Al[2]);
    split2(p3.x, p3.y, Ah[3], Al[3]);
}

// 12-mma group with dependency distance 4; per-acc order (hh, hl, lh) preserved
#define MMA12(A0h, A1h, A0l, A1l, BH, BL, C0, C1)          \
    do {                                                    \
        mma16(C0, A0h, BH[0], BH[1]);                       \
        mma16(C1, A1h, BH[0], BH[1]);                       \
        mma16((C0) + 4, A0h, BH[2], BH[3]);                 \
        mma16((C1) + 4, A1h, BH[2], BH[3]);                 \
        mma16(C0, A0h, BL[0], BL[1]);                       \
        mma16(C1, A1h, BL[0], BL[1]);                       \
        mma16((C0) + 4, A0h, BL[2], BL[3]);                 \
        mma16((C1) + 4, A1h, BL[2], BL[3]);                 \
        mma16(C0, A0l, BH[0], BH[1]);                       \
        mma16(C1, A1l, BH[0], BH[1]);                       \
        mma16((C0) + 4, A0l, BH[2], BH[3]);                 \
        mma16((C1) + 4, A1l, BH[2], BH[3]);                 \
    } while (0)

// ---------------------------------------------------------------------------
// prep kernel: fp32 weights -> packed bf16 hi/lo global scratch (natural order)
// ---------------------------------------------------------------------------
__global__ void prep_kernel(const float* __restrict__ W1, const float* __restrict__ W2,
                            const float* __restrict__ W3, const float* __restrict__ Whh) {
    int i = blockIdx.x * 256 + threadIdx.x;
    const int N1 = NCH1 * 256 * 8, N2 = 4 * 128 * 32, N3 = 64 * 64, N4 = 192 * 32;
    if (i < N1) {
        int kc = i >> 11, rem = i & 2047, n = rem >> 3, u = rem & 7;
        int k = kc * 16 + 2 * u;
        float v0 = (k < 361)     ? W1[n * 361 + k]     : 0.f;
        float v1 = (k + 1 < 361) ? W1[n * 361 + k + 1] : 0.f;
        split2(v0, v1, g_W1h[i], g_W1l[i]);
    } else if (i < N1 + N2) {
        int j = i - N1;
        int kc = j >> 12, rem = j & 4095, n = rem >> 5, u = rem & 31;
        int k = kc * 64 + 2 * u;
        split2(W2[n * 256 + k], W2[n * 256 + k + 1], g_W2h[j], g_W2l[j]);
    } else if (i < N1 + N2 + N3) {
        int j = i - N1 - N2;
        int n = j >> 6, u = j & 63;
        split2(W3[n * 128 + 2 * u], W3[n * 128 + 2 * u + 1], g_W3h[j], g_W3l[j]);
    } else if (i < N1 + N2 + N3 + N4) {
        int j = i - N1 - N2 - N3;
        int n = j >> 5, u = j & 31;
        split2(Whh[n * 64 + 2 * u], Whh[n * 64 + 2 * u + 1], g_Whh[j], g_Whl[j]);
    }
}

// ---------------------------------------------------------------------------
// fused kernel: MLP (3 GEMMs) + GRU. 128 rows/CTA, 512 threads.
// EXACT smem map of the 874us kernel.
// ---------------------------------------------------------------------------
__global__ void __launch_bounds__(512, 1) fused_kernel(
    const float* __restrict__ z,
    const float* __restrict__ b1, const float* __restrict__ b2, const float* __restrict__ b3,
    const float* __restrict__ Wih, const float* __restrict__ bih, const float* __restrict__ bhh,
    const float* __restrict__ Wo, const float* __restrict__ bo,
    float* __restrict__ out)
{
    extern __shared__ float sm[];
    unsigned* smu = (unsigned*)sm;
    const unsigned sb = (unsigned)__cvta_generic_to_shared(sm);

    const int tid = threadIdx.x, lane = tid & 31, wid = tid >> 5;
    const int g = lane >> 2, tg = lane & 3;
    const int wm = wid & 3, wn = wid >> 2;
    const int m0 = blockIdx.x * 128;

    const int arow = lane & 15;
    const int ak4  = (lane >> 4) * 4;
    const int brow = ((lane >> 4) << 3) + (lane & 7);
    const int bk4  = ((lane >> 3) & 1) * 4;

    unsigned* h1hi = smu;            // [128][132]
    unsigned* h1lo = smu + 16896;
    float*    zbuf = sm + 33792;     // 2 x [128][20]

    // ================= GEMM1: h1 = relu(z @ W1^T + b1) =================
    float acc1[2][8][4];
    #pragma unroll
    for (int a = 0; a < 2; a++)
        #pragma unroll
        for (int b = 0; b < 8; b++)
            #pragma unroll
            for (int c = 0; c < 4; c++) acc1[a][b][c] = 0.f;

    auto stage1 = [&](int buf, int kc) {
        const int k0 = kc * 16;
        {
            int m = tid >> 2, q4 = (tid & 3) * 4;
            int gk = k0 + q4;
            float* dst = zbuf + buf * 2560 + m * 20 + q4;
            const float* src = z + (size_t)(m0 + m) * 361 + gk;
            #pragma unroll
            for (int j = 0; j < 4; j++) {
                if (gk + j < 361) cpa4(dst + j, src + j);
                else              dst[j] = 0.f;
            }
        }
        {
            int n = tid >> 1, q4 = (tid & 1) * 4;
            cpa16(smu + 38912 + buf * 3072 + n * 12 + q4, g_W1h + kc * 2048 + n * 8 + q4);
            cpa16(smu + 45056 + buf * 3072 + n * 12 + q4, g_W1l + kc * 2048 + n * 8 + q4);
        }
    };

    const int w1_frag = (wn * 64 + brow) * 12 + bk4;

    stage1(0, 0); cp_commit();
    for (int kc = 0; kc < NCH1; kc++) {
        if (kc + 1 < NCH1) { stage1((kc + 1) & 1, kc + 1); cp_commit(); cp_wait<1>(); }
        else               { cp_wait<0>(); }
        __syncthreads();
        const float* az = zbuf + (kc & 1) * 2560 + (wm * 32) * 20;
        unsigned bh_addr = sb + 4u * (38912 + (kc & 1) * 3072 + w1_frag);
        unsigned bl_addr = bh_addr + 4u * 6144;
        unsigned Ah[2][4], Al[2][4];
        ldA_f32(az,           20, g, tg, Ah[0], Al[0]);
        ldA_f32(az + 16 * 20, 20, g, tg, Ah[1], Al[1]);
        #pragma unroll
        for (int p = 0; p < 4; p++) {
            unsigned bh[4], bl[4];
            ldsm4(bh[0], bh[1], bh[2], bh[3], bh_addr + 4u * (p * 16 * 12));
            ldsm4(bl[0], bl[1], bl[2], bl[3], bl_addr + 4u * (p * 16 * 12));
            MMA12(Ah[0], Ah[1], Al[0], Al[1], bh, bl, acc1[0][2*p], acc1[1][2*p]);
        }
        __syncthreads();
    }

    // prefetch W2 chunk 0 (over dead z/W1 region)
    auto stage2 = [&](int buf, int kc) {
        #pragma unroll
        for (int i = tid; i < 1024; i += 512) {
            int n = i >> 3, q4 = (i & 7) * 4;
            cpa16(smu + 33792 + buf * 4608 + n * 36 + q4, g_W2h + kc * 4096 + n * 32 + q4);
            cpa16(smu + 43008 + buf * 4608 + n * 36 + q4, g_W2l + kc * 4096 + n * 32 + q4);
        }
    };
    stage2(0, 0); cp_commit();

    // GEMM1 epilogue: h1 = relu(acc + b1) -> packed bf16 hi/lo
    #pragma unroll
    for (int mt = 0; mt < 2; mt++) {
        #pragma unroll
        for (int nt = 0; nt < 8; nt++) {
            int m = wm * 32 + mt * 16 + g;
            int n = wn * 64 + nt * 8 + 2 * tg;
            int nu = n >> 1;
            float bv0 = __ldg(b1 + n), bv1 = __ldg(b1 + n + 1);
            unsigned hi, lo;
            split2(relu_(acc1[mt][nt][0] + bv0), relu_(acc1[mt][nt][1] + bv1), hi, lo);
            h1hi[m * 132 + nu] = hi; h1lo[m * 132 + nu] = lo;
            split2(relu_(acc1[mt][nt][2] + bv0), relu_(acc1[mt][nt][3] + bv1), hi, lo);
            h1hi[(m + 8) * 132 + nu] = hi; h1lo[(m + 8) * 132 + nu] = lo;
        }
    }
    __syncthreads();

    // ================= GEMM2: h2 = relu(h1 @ W2^T + b2), 4 chunks of 64 ======
    float acc2[2][4][4];
    #pragma unroll
    for (int a = 0; a < 2; a++)
        #pragma unroll
        for (int b = 0; b < 4; b++)
            #pragma unroll
            for (int c = 0; c < 4; c++) acc2[a][b][c] = 0.f;

    const int h1_fragA = (wm * 32 + arow) * 132 + ak4;
    const int w2_fragB = (wn * 32 + brow) * 36 + bk4;

    for (int kc = 0; kc < 4; kc++) {
        if (kc + 1 < 4) { stage2((kc + 1) & 1, kc + 1); cp_commit(); cp_wait<1>(); }
        else            { cp_wait<0>(); }
        __syncthreads();
        unsigned w2h_addr = sb + 4u * (33792 + (kc & 1) * 4608 + w2_fragB);
        unsigned w2l_addr = w2h_addr + 4u * 9216;
        #pragma unroll
        for (int q = 0; q < 4; q++) {
            int u0 = kc * 32 + q * 8;
            unsigned Ah[2][4], Al[2][4];
            ldsm4(Ah[0][0], Ah[0][1], Ah[0][2], Ah[0][3], sb + 4u * (h1_fragA + u0));
            ldsm4(Ah[1][0], Ah[1][1], Ah[1][2], Ah[1][3], sb + 4u * (h1_fragA + 16 * 132 + u0));
            ldsm4(Al[0][0], Al[0][1], Al[0][2], Al[0][3], sb + 4u * (16896 + h1_fragA + u0));
            ldsm4(Al[1][0], Al[1][1], Al[1][2], Al[1][3], sb + 4u * (16896 + h1_fragA + 16 * 132 + u0));
            #pragma unroll
            for (int p = 0; p < 2; p++) {
                unsigned bh[4], bl[4];
                ldsm4(bh[0], bh[1], bh[2], bh[3], w2h_addr + 4u * (p * 16 * 36 + q * 8));
                ldsm4(bl[0], bl[1], bl[2], bl[3], w2l_addr + 4u * (p * 16 * 36 + q * 8));
                MMA12(Ah[0], Ah[1], Al[0], Al[1], bh, bl, acc2[0][2*p], acc2[1][2*p]);
            }
        }
        __syncthreads();
    }

    // ---- stage W3 @8704/13056 (over dead h1 rows) + h2 epilogue @33792 ----
    unsigned* w3h = smu + 8704;   // [64][68]
    unsigned* w3l = smu + 13056;
    #pragma unroll
    for (int i = tid; i < 2048; i += 512) {
        int half = i >> 10, j = i & 1023;
        int n = j >> 4, q4 = (j & 15) * 4;
        cpa16((half ? w3l : w3h) + n * 68 + q4, (half ? g_W3l : g_W3h) + n * 64 + q4);
    }
    cp_commit();

    unsigned* h2hi = smu + 33792;  // [128][68]
    unsigned* h2lo = smu + 42496;
    #pragma unroll
    for (int mt = 0; mt < 2; mt++) {
        #pragma unroll
        for (int nt = 0; nt < 4; nt++) {
            int m = wm * 32 + mt * 16 + g;
            int n = wn * 32 + nt * 8 + 2 * tg;
            int nu = n >> 1;
            float bv0 = __ldg(b2 + n), bv1 = __ldg(b2 + n + 1);
            unsigned hi, lo;
            split2(relu_(acc2[mt][nt][0] + bv0), relu_(acc2[mt][nt][1] + bv1), hi, lo);
            h2hi[m * 68 + nu] = hi; h2lo[m * 68 + nu] = lo;
            split2(relu_(acc2[mt][nt][2] + bv0), relu_(acc2[mt][nt][3] + bv1), hi, lo);
            h2hi[(m + 8) * 68 + nu] = hi; h2lo[(m + 8) * 68 + nu] = lo;
        }
    }
    cp_wait<0>();
    __syncthreads();

    // ================= GEMM3: h = relu(h2 @ W3^T + b3) =================
    float acc3[2][2][4];
    #pragma unroll
    for (int a = 0; a < 2; a++)
        #pragma unroll
        for (int b = 0; b < 2; b++)
            #pragma unroll
            for (int c = 0; c < 4; c++) acc3[a][b][c] = 0.f;

    const int h2_fragA = 33792 + (wm * 32 + arow) * 68 + ak4;
    const int w3_fragB = 8704 + (wn * 16 + brow) * 68 + bk4;

    #pragma unroll
    for (int q = 0; q < 8; q++) {
        int u0 = q * 8;
        unsigned Ah[2][4], Al[2][4];
        ldsm4(Ah[0][0], Ah[0][1], Ah[0][2], Ah[0][3], sb + 4u * (h2_fragA + u0));
        ldsm4(Ah[1][0], Ah[1][1], Ah[1][2], Ah[1][3], sb + 4u * (h2_fragA + 16 * 68 + u0));
        ldsm4(Al[0][0], Al[0][1], Al[0][2], Al[0][3], sb + 4u * (8704 + h2_fragA + u0));
        ldsm4(Al[1][0], Al[1][1], Al[1][2], Al[1][3], sb + 4u * (8704 + h2_fragA + 16 * 68 + u0));
        unsigned bh[4], bl[4];
        ldsm4(bh[0], bh[1], bh[2], bh[3], sb + 4u * (w3_fragB + u0));
        ldsm4(bl[0], bl[1], bl[2], bl[3], sb + 4u * (4352 + w3_fragB + u0));
        MMA12(Ah[0], Ah[1], Al[0], Al[1], bh, bl, acc3[0][0], acc3[1][0]);
    }
    __syncthreads();   // all w3/h2 reads done before overwrite

    // ================= GRU setup =================
    float*    h     = sm;                // [128][68] fp32
    float*    gh    = sm + 8704;         // [128][196]
    unsigned* whhh  = smu + 33792;       // [192][36]
    unsigned* whhl  = smu + 40704;
    float*    wih   = sm + 47616;        // [192][2]
    float*    sbih  = sm + 48000;
    float*    sbhh  = sm + 48192;
    float*    swo   = sm + 48384;
    float*    sbo   = sm + 48512;
    float*    x     = sm + 48516;        // [128][2]
    float*    xh    = sm + 48772;        // [128][20]

    #pragma unroll
    for (int i = tid; i < 3072; i += 512) {
        int half = (i >= 1536), j = half ? i - 1536 : i;
        int n = j >> 3, q4 = (j & 7) * 4;
        cpa16((half ? whhl : whhh) + n * 36 + q4, (half ? g_Whl : g_Whh) + n * 32 + q4);
    }
    cp_commit();
    if (tid < 384) wih[tid] = Wih[tid];
    if (tid < 192) { sbih[tid] = bih[tid]; sbhh[tid] = bhh[tid]; }
    if (tid < 128) swo[tid] = Wo[tid];
    if (tid < 2)   sbo[tid] = bo[tid];
    if (tid < 256) x[tid] = 0.f;

    // GEMM3 epilogue: h = relu(acc + b3) fp32 @0
    #pragma unroll
    for (int mt = 0; mt < 2; mt++) {
        #pragma unroll
        for (int nt = 0; nt < 2; nt++) {
            int m = wm * 32 + mt * 16 + g;
            int n = wn * 16 + nt * 8 + 2 * tg;
            float bv0 = __ldg(b3 + n), bv1 = __ldg(b3 + n + 1);
            h[m * 68 + n]           = relu_(acc3[mt][nt][0] + bv0);
            h[m * 68 + n + 1]       = relu_(acc3[mt][nt][1] + bv1);
            h[(m + 8) * 68 + n]     = relu_(acc3[mt][nt][2] + bv0);
            h[(m + 8) * 68 + n + 1] = relu_(acc3[mt][nt][3] + bv1);
        }
    }
    cp_wait<0>();
    __syncthreads();

    // ================= GRU loop =================
    // Step t: mma phase computes gh(h); CONCURRENTLY Wo for step t-1 runs on the
    // same (stable) h and updates x/xh[t-1] before the sync -> gates_t sees x_{t-1}.
    const int whh_fragB = 33792 + (wn * 48 + brow) * 36 + bk4;
    for (int t = 0; t < PLEN; t++) {
        float acc[2][6][4];
        #pragma unroll
        for (int a = 0; a < 2; a++)
            #pragma unroll
            for (int b = 0; b < 6; b++)
                #pragma unroll
                for (int c = 0; c < 4; c++) acc[a][b][c] = 0.f;

        #pragma unroll
        for (int q = 0; q < 4; q++) {
            unsigned Ah[2][4], Al[2][4];
            ldA_f32(h + (wm * 32) * 68 + q * 16,      68, g, tg, Ah[0], Al[0]);
            ldA_f32(h + (wm * 32 + 16) * 68 + q * 16, 68, g, tg, Ah[1], Al[1]);
            #pragma unroll
            for (int p = 0; p < 3; p++) {
                unsigned bh[4], bl[4];
                ldsm4(bh[0], bh[1], bh[2], bh[3], sb + 4u * (whh_fragB + p * 16 * 36 + q * 8));
                ldsm4(bl[0], bl[1], bl[2], bl[3], sb + 4u * (6912 + whh_fragB + p * 16 * 36 + q * 8));
                MMA12(Ah[0], Ah[1], Al[0], Al[1], bh, bl, acc[0][2*p], acc[1][2*p]);
            }
        }
        #pragma unroll
        for (int mt = 0; mt < 2; mt++) {
            #pragma unroll
            for (int nt = 0; nt < 6; nt++) {
                int m = wm * 32 + mt * 16 + g;
                int n = wn * 48 + nt * 8 + 2 * tg;
                *(float2*)&gh[m * 196 + n]       = make_float2(acc[mt][nt][0], acc[mt][nt][1]);
                *(float2*)&gh[(m + 8) * 196 + n] = make_float2(acc[mt][nt][2], acc[mt][nt][3]);
            }
        }
        // overlapped Wo for step t-1 (h is the post-gates_{t-1} state, untouched here)
        if (t > 0 && tid < 256) {
            int r = tid >> 1, o = tid & 1;
            float s = sbo[o];
            const float* hr = h + r * 68;
            const float* wr = swo + o * 64;
            #pragma unroll 8
            for (int j = 0; j < 64; j++) s += hr[j] * wr[j];
            float xv = x[r * 2 + o] + s;
            x[r * 2 + o] = xv;
            xh[r * 20 + (t - 1) * 2 + o] = xv;
        }
        __syncthreads();

        // gates (fast approx sigmoid/tanh), in-place h update
        #pragma unroll
        for (int e = tid; e < 8192; e += 512) {
            int r = e >> 6, j = e & 63;
            float x0v = x[r * 2], x1v = x[r * 2 + 1];
            float ghr = gh[r * 196 + j]       + sbhh[j];
            float ghz = gh[r * 196 + j + 64]  + sbhh[j + 64];
            float ghn = gh[r * 196 + j + 128] + sbhh[j + 128];
            float gir = x0v * wih[j * 2]           + x1v * wih[j * 2 + 1]           + sbih[j];
            float giz = x0v * wih[(j + 64) * 2]    + x1v * wih[(j + 64) * 2 + 1]    + sbih[j + 64];
            float gin = x0v * wih[(j + 128) * 2]   + x1v * wih[(j + 128) * 2 + 1]   + sbih[j + 128];
            float rg = 0.5f * tanhapx(0.5f * (gir + ghr)) + 0.5f;
            float zg = 0.5f * tanhapx(0.5f * (giz + ghz)) + 0.5f;
            float ng = tanhapx(gin + rg * ghn);
            float hv = h[r * 68 + j];
            h[r * 68 + j] = (1.f - zg) * ng + zg * hv;
        }
        __syncthreads();
    }

    // final Wo (step PLEN-1)
    if (tid < 256) {
        int r = tid >> 1, o = tid & 1;
        float s = sbo[o];
        const float* hr = h + r * 68;
        const float* wr = swo + o * 64;
        #pragma unroll 8
        for (int j = 0; j < 64; j++) s += hr[j] * wr[j];
        float xv = x[r * 2 + o] + s;
        xh[r * 20 + (PLEN - 1) * 2 + o] = xv;
    }
    __syncthreads();

    // coalesced output: out[b, t, o]
    #pragma unroll
    for (int i = tid; i < 640; i += 512) {
        int r = i / 5, q = (i % 5) * 4;
        *(float4*)&out[(size_t)(m0 + r) * 20 + q] = *(const float4*)&xh[r * 20 + q];
    }
}

// ---------------------------------------------------------------------------
extern "C" void kernel_launch(void* const* d_in, const int* in_sizes, int n_in,
                              void* d_out, int out_size)
{
    const float* z   = (const float*)d_in[0];
    const float* W1  = (const float*)d_in[1];
    const float* b1  = (const float*)d_in[2];
    const float* W2  = (const float*)d_in[3];
    const float* b2  = (const float*)d_in[4];
    const float* W3  = (const float*)d_in[5];
    const float* b3  = (const float*)d_in[6];
    const float* Wih = (const float*)d_in[7];
    const float* Whh = (const float*)d_in[8];
    const float* bih = (const float*)d_in[9];
    const float* bhh = (const float*)d_in[10];
    const float* Wo  = (const float*)d_in[11];
    const float* bo  = (const float*)d_in[12];
    float* out = (float*)d_out;

    const int smem = 52224 * 4;  // 208896 B
    cudaFuncSetAttribute(fused_kernel, cudaFuncAttributeMaxDynamicSharedMemorySize, smem);

    prep_kernel<<<288, 256>>>(W1, W2, W3, Whh);
    fused_kernel<<<BS / 128, 512, smem>>>(z, b1, b2, b3, Wih, bih, bhh, Wo, bo, out);
}

// round 13
// speedup vs baseline: 1.4646x; 1.0299x over previous
#include <cuda_runtime.h>
#include <cuda_bf16.h>

#define BS 131072
#define PLEN 10
#define NCH1 23   // GEMM1: K=361 padded to 368 = 23 chunks of 16

// -------- pre-split weights: packed bf16 (2 per u32 along k), hi & lo, natural order
__device__ __align__(16) unsigned g_W1h[NCH1 * 256 * 8], g_W1l[NCH1 * 256 * 8]; // [kc][n][8]
__device__ __align__(16) unsigned g_W2h[4 * 128 * 32],   g_W2l[4 * 128 * 32];   // [kc][n][32]
__device__ __align__(16) unsigned g_W3h[64 * 64],        g_W3l[64 * 64];        // [n][64]
__device__ __align__(16) unsigned g_Whh[192 * 32],       g_Whl[192 * 32];       // [n][32]

// ---------------------------------------------------------------------------
__device__ __forceinline__ unsigned packbf(float lo, float hi) {
    unsigned r;
    asm("cvt.rn.bf16x2.f32 %0, %1, %2;" : "=r"(r) : "f"(hi), "f"(lo));
    return r;
}
__device__ __forceinline__ void split2(float v0, float v1, unsigned& hi, unsigned& lo) {
    hi = packbf(v0, v1);
    float h0 = __uint_as_float(hi << 16);
    float h1 = __uint_as_float(hi & 0xffff0000u);
    lo = packbf(v0 - h0, v1 - h1);
}
__device__ __forceinline__ float bflo(unsigned u) { return __uint_as_float(u << 16); }
__device__ __forceinline__ float bfhi(unsigned u) { return __uint_as_float(u & 0xffff0000u); }
__device__ __forceinline__ float relu_(float v) { return v > 0.f ? v : 0.f; }
__device__ __forceinline__ float tanhapx(float x) {
    float y; asm("tanh.approx.f32 %0, %1;" : "=f"(y) : "f"(x)); return y;
}

__device__ __forceinline__ void mma16(float* c, const unsigned* a, unsigned b0, unsigned b1) {
    asm("mma.sync.aligned.m16n8k16.row.col.f32.bf16.bf16.f32 "
        "{%0,%1,%2,%3},{%4,%5,%6,%7},{%8,%9},{%0,%1,%2,%3};"
        : "+f"(c[0]), "+f"(c[1]), "+f"(c[2]), "+f"(c[3])
        : "r"(a[0]), "r"(a[1]), "r"(a[2]), "r"(a[3]), "r"(b0), "r"(b1));
}

__device__ __forceinline__ void ldsm4(unsigned& r0, unsigned& r1, unsigned& r2, unsigned& r3,
                                      unsigned addr) {
    asm volatile("ldmatrix.sync.aligned.m8n8.x4.shared.b16 {%0,%1,%2,%3}, [%4];"
        : "=r"(r0), "=r"(r1), "=r"(r2), "=r"(r3) : "r"(addr));
}

__device__ __forceinline__ void cpa4(void* s, const void* g) {
    unsigned a = (unsigned)__cvta_generic_to_shared(s);
    asm volatile("cp.async.ca.shared.global [%0],[%1],4;" :: "r"(a), "l"(g) : "memory");
}
__device__ __forceinline__ void cpa16(void* s, const void* g) {
    unsigned a = (unsigned)__cvta_generic_to_shared(s);
    asm volatile("cp.async.cg.shared.global [%0],[%1],16;" :: "r"(a), "l"(g) : "memory");
}
__device__ __forceinline__ void cp_commit() { asm volatile("cp.async.commit_group;" ::: "memory"); }
template <int N>
__device__ __forceinline__ void cp_wait() { asm volatile("cp.async.wait_group %0;" :: "n"(N) : "memory"); }

// load fp32 A tile fragment (16 rows) and split to bf16 hi/lo frags (GEMM1 z only)
__device__ __forceinline__ void ldA_f32(const float* base, int stride, int g, int tg,
                                        unsigned* Ah, unsigned* Al) {
    float2 p0 = *(const float2*)(base + g * stride + 2 * tg);
    float2 p1 = *(const float2*)(base + (g + 8) * stride + 2 * tg);
    float2 p2 = *(const float2*)(base + g * stride + 2 * tg + 8);
    float2 p3 = *(const float2*)(base + (g + 8) * stride + 2 * tg + 8);
    split2(p0.x, p0.y, Ah[0], Al[0]);
    split2(p1.x, p1.y, Ah[1], Al[1]);
    split2(p2.x, p2.y, Ah[2], Al[2]);
    split2(p3.x, p3.y, Ah[3], Al[3]);
}

// 12-mma group, dependency distance 4; per-acc order (hh, hl, lh) preserved
#define MMA12(A0h, A1h, A0l, A1l, BH, BL, C0, C1)          \
    do {                                                    \
        mma16(C0, A0h, BH[0], BH[1]);                       \
        mma16(C1, A1h, BH[0], BH[1]);                       \
        mma16((C0) + 4, A0h, BH[2], BH[3]);                 \
        mma16((C1) + 4, A1h, BH[2], BH[3]);                 \
        mma16(C0, A0h, BL[0], BL[1]);                       \
        mma16(C1, A1h, BL[0], BL[1]);                       \
        mma16((C0) + 4, A0h, BL[2], BL[3]);                 \
        mma16((C1) + 4, A1h, BL[2], BL[3]);                 \
        mma16(C0, A0l, BH[0], BH[1]);                       \
        mma16(C1, A1l, BH[0], BH[1]);                       \
        mma16((C0) + 4, A0l, BH[2], BH[3]);                 \
        mma16((C1) + 4, A1l, BH[2], BH[3]);                 \
    } while (0)

// ---------------------------------------------------------------------------
__global__ void prep_kernel(const float* __restrict__ W1, const float* __restrict__ W2,
                            const float* __restrict__ W3, const float* __restrict__ Whh) {
    int i = blockIdx.x * 256 + threadIdx.x;
    const int N1 = NCH1 * 256 * 8, N2 = 4 * 128 * 32, N3 = 64 * 64, N4 = 192 * 32;
    if (i < N1) {
        int kc = i >> 11, rem = i & 2047, n = rem >> 3, u = rem & 7;
        int k = kc * 16 + 2 * u;
        float v0 = (k < 361)     ? W1[n * 361 + k]     : 0.f;
        float v1 = (k + 1 < 361) ? W1[n * 361 + k + 1] : 0.f;
        split2(v0, v1, g_W1h[i], g_W1l[i]);
    } else if (i < N1 + N2) {
        int j = i - N1;
        int kc = j >> 12, rem = j & 4095, n = rem >> 5, u = rem & 31;
        int k = kc * 64 + 2 * u;
        split2(W2[n * 256 + k], W2[n * 256 + k + 1], g_W2h[j], g_W2l[j]);
    } else if (i < N1 + N2 + N3) {
        int j = i - N1 - N2;
        int n = j >> 6, u = j & 63;
        split2(W3[n * 128 + 2 * u], W3[n * 128 + 2 * u + 1], g_W3h[j], g_W3l[j]);
    } else if (i < N1 + N2 + N3 + N4) {
        int j = i - N1 - N2 - N3;
        int n = j >> 5, u = j & 31;
        split2(Whh[n * 64 + 2 * u], Whh[n * 64 + 2 * u + 1], g_Whh[j], g_Whl[j]);
    }
}

// ---------------------------------------------------------------------------
// fused kernel. MLP identical to the 825us kernel. GRU: packed h + vectorized gates.
// GRU smem (u32): hhi [128][36] @0, hlo @4608, whhh [192][36] @9216, whhl @16128,
//   gh fp32 [128][196] @23040, wih @48128, sbrz @48512, sbin @48640, sbhn @48704,
//   swo @48768, sbo @48896, x @48900, xh [128][20] @49156  (..51716)
// ---------------------------------------------------------------------------
__global__ void __launch_bounds__(512, 1) fused_kernel(
    const float* __restrict__ z,
    const float* __restrict__ b1, const float* __restrict__ b2, const float* __restrict__ b3,
    const float* __restrict__ Wih, const float* __restrict__ bih, const float* __restrict__ bhh,
    const float* __restrict__ Wo, const float* __restrict__ bo,
    float* __restrict__ out)
{
    extern __shared__ float sm[];
    unsigned* smu = (unsigned*)sm;
    const unsigned sb = (unsigned)__cvta_generic_to_shared(sm);

    const int tid = threadIdx.x, lane = tid & 31, wid = tid >> 5;
    const int g = lane >> 2, tg = lane & 3;
    const int wm = wid & 3, wn = wid >> 2;
    const int m0 = blockIdx.x * 128;

    const int arow = lane & 15;
    const int ak4  = (lane >> 4) * 4;
    const int brow = ((lane >> 4) << 3) + (lane & 7);
    const int bk4  = ((lane >> 3) & 1) * 4;

    unsigned* h1hi = smu;            // [128][132]
    unsigned* h1lo = smu + 16896;
    float*    zbuf = sm + 33792;     // 2 x [128][20]

    // ================= GEMM1: h1 = relu(z @ W1^T + b1) =================
    float acc1[2][8][4];
    #pragma unroll
    for (int a = 0; a < 2; a++)
        #pragma unroll
        for (int b = 0; b < 8; b++)
            #pragma unroll
            for (int c = 0; c < 4; c++) acc1[a][b][c] = 0.f;

    auto stage1 = [&](int buf, int kc) {
        const int k0 = kc * 16;
        {
            int m = tid >> 2, q4 = (tid & 3) * 4;
            int gk = k0 + q4;
            float* dst = zbuf + buf * 2560 + m * 20 + q4;
            const float* src = z + (size_t)(m0 + m) * 361 + gk;
            #pragma unroll
            for (int j = 0; j < 4; j++) {
                if (gk + j < 361) cpa4(dst + j, src + j);
                else              dst[j] = 0.f;
            }
        }
        {
            int n = tid >> 1, q4 = (tid & 1) * 4;
            cpa16(smu + 38912 + buf * 3072 + n * 12 + q4, g_W1h + kc * 2048 + n * 8 + q4);
            cpa16(smu + 45056 + buf * 3072 + n * 12 + q4, g_W1l + kc * 2048 + n * 8 + q4);
        }
    };

    const int w1_frag = (wn * 64 + brow) * 12 + bk4;

    stage1(0, 0); cp_commit();
    for (int kc = 0; kc < NCH1; kc++) {
        if (kc + 1 < NCH1) { stage1((kc + 1) & 1, kc + 1); cp_commit(); cp_wait<1>(); }
        else               { cp_wait<0>(); }
        __syncthreads();
        const float* az = zbuf + (kc & 1) * 2560 + (wm * 32) * 20;
        unsigned bh_addr = sb + 4u * (38912 + (kc & 1) * 3072 + w1_frag);
        unsigned bl_addr = bh_addr + 4u * 6144;
        unsigned Ah[2][4], Al[2][4];
        ldA_f32(az,           20, g, tg, Ah[0], Al[0]);
        ldA_f32(az + 16 * 20, 20, g, tg, Ah[1], Al[1]);
        #pragma unroll
        for (int p = 0; p < 4; p++) {
            unsigned bh[4], bl[4];
            ldsm4(bh[0], bh[1], bh[2], bh[3], bh_addr + 4u * (p * 16 * 12));
            ldsm4(bl[0], bl[1], bl[2], bl[3], bl_addr + 4u * (p * 16 * 12));
            MMA12(Ah[0], Ah[1], Al[0], Al[1], bh, bl, acc1[0][2*p], acc1[1][2*p]);
        }
        __syncthreads();
    }

    // prefetch W2 chunk 0
    auto stage2 = [&](int buf, int kc) {
        #pragma unroll
        for (int i = tid; i < 1024; i += 512) {
            int n = i >> 3, q4 = (i & 7) * 4;
            cpa16(smu + 33792 + buf * 4608 + n * 36 + q4, g_W2h + kc * 4096 + n * 32 + q4);
            cpa16(smu + 43008 + buf * 4608 + n * 36 + q4, g_W2l + kc * 4096 + n * 32 + q4);
        }
    };
    stage2(0, 0); cp_commit();

    // GEMM1 epilogue -> packed h1
    #pragma unroll
    for (int mt = 0; mt < 2; mt++) {
        #pragma unroll
        for (int nt = 0; nt < 8; nt++) {
            int m = wm * 32 + mt * 16 + g;
            int n = wn * 64 + nt * 8 + 2 * tg;
            int nu = n >> 1;
            float bv0 = __ldg(b1 + n), bv1 = __ldg(b1 + n + 1);
            unsigned hi, lo;
            split2(relu_(acc1[mt][nt][0] + bv0), relu_(acc1[mt][nt][1] + bv1), hi, lo);
            h1hi[m * 132 + nu] = hi; h1lo[m * 132 + nu] = lo;
            split2(relu_(acc1[mt][nt][2] + bv0), relu_(acc1[mt][nt][3] + bv1), hi, lo);
            h1hi[(m + 8) * 132 + nu] = hi; h1lo[(m + 8) * 132 + nu] = lo;
        }
    }
    __syncthreads();

    // ================= GEMM2 =================
    float acc2[2][4][4];
    #pragma unroll
    for (int a = 0; a < 2; a++)
        #pragma unroll
        for (int b = 0; b < 4; b++)
            #pragma unroll
            for (int c = 0; c < 4; c++) acc2[a][b][c] = 0.f;

    const int h1_fragA = (wm * 32 + arow) * 132 + ak4;
    const int w2_fragB = (wn * 32 + brow) * 36 + bk4;

    for (int kc = 0; kc < 4; kc++) {
        if (kc + 1 < 4) { stage2((kc + 1) & 1, kc + 1); cp_commit(); cp_wait<1>(); }
        else            { cp_wait<0>(); }
        __syncthreads();
        unsigned w2h_addr = sb + 4u * (33792 + (kc & 1) * 4608 + w2_fragB);
        unsigned w2l_addr = w2h_addr + 4u * 9216;
        #pragma unroll
        for (int q = 0; q < 4; q++) {
            int u0 = kc * 32 + q * 8;
            unsigned Ah[2][4], Al[2][4];
            ldsm4(Ah[0][0], Ah[0][1], Ah[0][2], Ah[0][3], sb + 4u * (h1_fragA + u0));
            ldsm4(Ah[1][0], Ah[1][1], Ah[1][2], Ah[1][3], sb + 4u * (h1_fragA + 16 * 132 + u0));
            ldsm4(Al[0][0], Al[0][1], Al[0][2], Al[0][3], sb + 4u * (16896 + h1_fragA + u0));
            ldsm4(Al[1][0], Al[1][1], Al[1][2], Al[1][3], sb + 4u * (16896 + h1_fragA + 16 * 132 + u0));
            #pragma unroll
            for (int p = 0; p < 2; p++) {
                unsigned bh[4], bl[4];
                ldsm4(bh[0], bh[1], bh[2], bh[3], w2h_addr + 4u * (p * 16 * 36 + q * 8));
                ldsm4(bl[0], bl[1], bl[2], bl[3], w2l_addr + 4u * (p * 16 * 36 + q * 8));
                MMA12(Ah[0], Ah[1], Al[0], Al[1], bh, bl, acc2[0][2*p], acc2[1][2*p]);
            }
        }
        __syncthreads();
    }

    // ---- stage W3 @8704/13056 + h2 epilogue @33792 ----
    unsigned* w3h = smu + 8704;   // [64][68]
    unsigned* w3l = smu + 13056;
    #pragma unroll
    for (int i = tid; i < 2048; i += 512) {
        int half = i >> 10, j = i & 1023;
        int n = j >> 4, q4 = (j & 15) * 4;
        cpa16((half ? w3l : w3h) + n * 68 + q4, (half ? g_W3l : g_W3h) + n * 64 + q4);
    }
    cp_commit();

    unsigned* h2hi = smu + 33792;  // [128][68]
    unsigned* h2lo = smu + 42496;
    #pragma unroll
    for (int mt = 0; mt < 2; mt++) {
        #pragma unroll
        for (int nt = 0; nt < 4; nt++) {
            int m = wm * 32 + mt * 16 + g;
            int n = wn * 32 + nt * 8 + 2 * tg;
            int nu = n >> 1;
            float bv0 = __ldg(b2 + n), bv1 = __ldg(b2 + n + 1);
            unsigned hi, lo;
            split2(relu_(acc2[mt][nt][0] + bv0), relu_(acc2[mt][nt][1] + bv1), hi, lo);
            h2hi[m * 68 + nu] = hi; h2lo[m * 68 + nu] = lo;
            split2(relu_(acc2[mt][nt][2] + bv0), relu_(acc2[mt][nt][3] + bv1), hi, lo);
            h2hi[(m + 8) * 68 + nu] = hi; h2lo[(m + 8) * 68 + nu] = lo;
        }
    }
    cp_wait<0>();
    __syncthreads();

    // ================= GEMM3 =================
    float acc3[2][2][4];
    #pragma unroll
    for (int a = 0; a < 2; a++)
        #pragma unroll
        for (int b = 0; b < 2; b++)
            #pragma unroll
            for (int c = 0; c < 4; c++) acc3[a][b][c] = 0.f;

    const int h2_fragA = 33792 + (wm * 32 + arow) * 68 + ak4;
    const int w3_fragB = 8704 + (wn * 16 + brow) * 68 + bk4;

    #pragma unroll
    for (int q = 0; q < 8; q++) {
        int u0 = q * 8;
        unsigned Ah[2][4], Al[2][4];
        ldsm4(Ah[0][0], Ah[0][1], Ah[0][2], Ah[0][3], sb + 4u * (h2_fragA + u0));
        ldsm4(Ah[1][0], Ah[1][1], Ah[1][2], Ah[1][3], sb + 4u * (h2_fragA + 16 * 68 + u0));
        ldsm4(Al[0][0], Al[0][1], Al[0][2], Al[0][3], sb + 4u * (8704 + h2_fragA + u0));
        ldsm4(Al[1][0], Al[1][1], Al[1][2], Al[1][3], sb + 4u * (8704 + h2_fragA + 16 * 68 + u0));
        unsigned bh[4], bl[4];
        ldsm4(bh[0], bh[1], bh[2], bh[3], sb + 4u * (w3_fragB + u0));
        ldsm4(bl[0], bl[1], bl[2], bl[3], sb + 4u * (4352 + w3_fragB + u0));
        MMA12(Ah[0], Ah[1], Al[0], Al[1], bh, bl, acc3[0][0], acc3[1][0]);
    }
    __syncthreads();   // all w3/h2 reads done before overwrite

    // ================= GRU setup =================
    unsigned* hhi  = smu;            // [128][36]
    unsigned* hlo  = smu + 4608;
    unsigned* whhh = smu + 9216;     // [192][36]
    unsigned* whhl = smu + 16128;
    float*    gh   = sm + 23040;     // [128][196]
    float*    wih  = sm + 48128;     // [192][2]
    float*    sbrz = sm + 48512;     // [128] = bih+bhh for r,z gates
    float*    sbin = sm + 48640;     // [64]  = bih for n gate
    float*    sbhn = sm + 48704;     // [64]  = bhh for n gate
    float*    swo  = sm + 48768;
    float*    sbo  = sm + 48896;
    float*    x    = sm + 48900;     // [128][2]
    float*    xh   = sm + 49156;     // [128][20]

    #pragma unroll
    for (int i = tid; i < 3072; i += 512) {
        int half = (i >= 1536), j = half ? i - 1536 : i;
        int n = j >> 3, q4 = (j & 7) * 4;
        cpa16((half ? whhl : whhh) + n * 36 + q4, (half ? g_Whl : g_Whh) + n * 32 + q4);
    }
    cp_commit();
    if (tid < 384) wih[tid] = Wih[tid];
    if (tid < 128) sbrz[tid] = bih[tid] + bhh[tid];
    if (tid >= 128 && tid < 192) { sbin[tid - 128] = bih[tid]; sbhn[tid - 128] = bhh[tid]; }
    if (tid >= 192 && tid < 320) swo[tid - 192] = Wo[tid - 192];
    if (tid >= 320 && tid < 322) sbo[tid - 320] = bo[tid - 320];
    if (tid < 256) x[tid] = 0.f;

    // GEMM3 epilogue -> packed h
    #pragma unroll
    for (int mt = 0; mt < 2; mt++) {
        #pragma unroll
        for (int nt = 0; nt < 2; nt++) {
            int m = wm * 32 + mt * 16 + g;
            int n = wn * 16 + nt * 8 + 2 * tg;
            int nu = n >> 1;
            float bv0 = __ldg(b3 + n), bv1 = __ldg(b3 + n + 1);
            unsigned hi, lo;
            split2(relu_(acc3[mt][nt][0] + bv0), relu_(acc3[mt][nt][1] + bv1), hi, lo);
            hhi[m * 36 + nu] = hi; hlo[m * 36 + nu] = lo;
            split2(relu_(acc3[mt][nt][2] + bv0), relu_(acc3[mt][nt][3] + bv1), hi, lo);
            hhi[(m + 8) * 36 + nu] = hi; hlo[(m + 8) * 36 + nu] = lo;
        }
    }
    cp_wait<0>();
    __syncthreads();

    // ================= GRU loop =================
    const int h_fragA   = (wm * 32 + arow) * 36 + ak4;
    const int whh_fragB = 9216 + (wn * 48 + brow) * 36 + bk4;
    const int gcol = tid & 31;    // gate u32 col
    const int grb  = tid >> 5;    // gate row block (8 rows)

    for (int t = 0; t < PLEN; t++) {
        // ---- gh = h @ Whh^T (A via ldmatrix from packed h) ----
        float acc[2][6][4];
        #pragma unroll
        for (int a = 0; a < 2; a++)
            #pragma unroll
            for (int b = 0; b < 6; b++)
                #pragma unroll
                for (int c = 0; c < 4; c++) acc[a][b][c] = 0.f;

        #pragma unroll
        for (int q = 0; q < 4; q++) {
            unsigned Ah[2][4], Al[2][4];
            ldsm4(Ah[0][0], Ah[0][1], Ah[0][2], Ah[0][3], sb + 4u * (h_fragA + q * 8));
            ldsm4(Ah[1][0], Ah[1][1], Ah[1][2], Ah[1][3], sb + 4u * (h_fragA + 16 * 36 + q * 8));
            ldsm4(Al[0][0], Al[0][1], Al[0][2], Al[0][3], sb + 4u * (4608 + h_fragA + q * 8));
            ldsm4(Al[1][0], Al[1][1], Al[1][2], Al[1][3], sb + 4u * (4608 + h_fragA + 16 * 36 + q * 8));
            #pragma unroll
            for (int p = 0; p < 3; p++) {
                unsigned bh[4], bl[4];
                ldsm4(bh[0], bh[1], bh[2], bh[3], sb + 4u * (whh_fragB + p * 16 * 36 + q * 8));
                ldsm4(bl[0], bl[1], bl[2], bl[3], sb + 4u * (6912 + whh_fragB + p * 16 * 36 + q * 8));
                MMA12(Ah[0], Ah[1], Al[0], Al[1], bh, bl, acc[0][2*p], acc[1][2*p]);
            }
        }
        #pragma unroll
        for (int mt = 0; mt < 2; mt++) {
            #pragma unroll
            for (int nt = 0; nt < 6; nt++) {
                int m = wm * 32 + mt * 16 + g;
                int n = wn * 48 + nt * 8 + 2 * tg;
                *(float2*)&gh[m * 196 + n]       = make_float2(acc[mt][nt][0], acc[mt][nt][1]);
                *(float2*)&gh[(m + 8) * 196 + n] = make_float2(acc[mt][nt][2], acc[mt][nt][3]);
            }
        }
        // overlapped Wo for step t-1 (h stable during mma phase)
        if (t > 0 && tid < 256) {
            int r = tid >> 1, o = tid & 1;
            float s = sbo[o];
            const float* wr = swo + o * 64;
            #pragma unroll 8
            for (int c = 0; c < 32; c++) {
                unsigned uh = hhi[r * 36 + c], ul = hlo[r * 36 + c];
                s += (bflo(uh) + bflo(ul)) * wr[2 * c];
                s += (bfhi(uh) + bfhi(ul)) * wr[2 * c + 1];
            }
            float xv = x[r * 2 + o] + s;
            x[r * 2 + o] = xv;
            xh[r * 20 + (t - 1) * 2 + o] = xv;
        }
        __syncthreads();

        // ---- gates: 8 rows x 2 cols per thread, vectorized loads ----
        {
            float4 wr4 = *(const float4*)&wih[4 * gcol];
            float4 wz4 = *(const float4*)&wih[128 + 4 * gcol];
            float4 wn4 = *(const float4*)&wih[256 + 4 * gcol];
            float2 brz_r = *(const float2*)&sbrz[2 * gcol];
            float2 brz_z = *(const float2*)&sbrz[64 + 2 * gcol];
            float2 bin2  = *(const float2*)&sbin[2 * gcol];
            float2 bhn2  = *(const float2*)&sbhn[2 * gcol];
            #pragma unroll
            for (int rr = 0; rr < 8; rr++) {
                int r = grb * 8 + rr;
                float x0v = x[2 * r], x1v = x[2 * r + 1];
                unsigned uh = hhi[r * 36 + gcol], ul = hlo[r * 36 + gcol];
                float hv0 = bflo(uh) + bflo(ul);
                float hv1 = bfhi(uh) + bfhi(ul);
                float2 g_r = *(const float2*)&gh[r * 196 + 2 * gcol];
                float2 g_z = *(const float2*)&gh[r * 196 + 64 + 2 * gcol];
                float2 g_n = *(const float2*)&gh[r * 196 + 128 + 2 * gcol];
                float rg0 = 0.5f * tanhapx(0.5f * (x0v * wr4.x + x1v * wr4.y + brz_r.x + g_r.x)) + 0.5f;
                float rg1 = 0.5f * tanhapx(0.5f * (x0v * wr4.z + x1v * wr4.w + brz_r.y + g_r.y)) + 0.5f;
                float zg0 = 0.5f * tanhapx(0.5f * (x0v * wz4.x + x1v * wz4.y + brz_z.x + g_z.x)) + 0.5f;
                float zg1 = 0.5f * tanhapx(0.5f * (x0v * wz4.z + x1v * wz4.w + brz_z.y + g_z.y)) + 0.5f;
                float ng0 = tanhapx(x0v * wn4.x + x1v * wn4.y + bin2.x + rg0 * (g_n.x + bhn2.x));
                float ng1 = tanhapx(x0v * wn4.z + x1v * wn4.w + bin2.y + rg1 * (g_n.y + bhn2.y));
                float hn0 = (1.f - zg0) * ng0 + zg0 * hv0;
                float hn1 = (1.f - zg1) * ng1 + zg1 * hv1;
                unsigned nhi, nlo;
                split2(hn0, hn1, nhi, nlo);
                hhi[r * 36 + gcol] = nhi; hlo[r * 36 + gcol] = nlo;
            }
        }
        __syncthreads();
    }

    // final Wo (step PLEN-1)
    if (tid < 256) {
        int r = tid >> 1, o = tid & 1;
        float s = sbo[o];
        const float* wr = swo + o * 64;
        #pragma unroll 8
        for (int c = 0; c < 32; c++) {
            unsigned uh = hhi[r * 36 + c], ul = hlo[r * 36 + c];
            s += (bflo(uh) + bflo(ul)) * wr[2 * c];
            s += (bfhi(uh) + bfhi(ul)) * wr[2 * c + 1];
        }
        float xv = x[r * 2 + o] + s;
        xh[r * 20 + (PLEN - 1) * 2 + o] = xv;
    }
    __syncthreads();

    // coalesced output: out[b, t, o]
    #pragma unroll
    for (int i = tid; i < 640; i += 512) {
        int r = i / 5, q = (i % 5) * 4;
        *(float4*)&out[(size_t)(m0 + r) * 20 + q] = *(const float4*)&xh[r * 20 + q];
    }
}

// ---------------------------------------------------------------------------
extern "C" void kernel_launch(void* const* d_in, const int* in_sizes, int n_in,
                              void* d_out, int out_size)
{
    const float* z   = (const float*)d_in[0];
    const float* W1  = (const float*)d_in[1];
    const float* b1  = (const float*)d_in[2];
    const float* W2  = (const float*)d_in[3];
    const float* b2  = (const float*)d_in[4];
    const float* W3  = (const float*)d_in[5];
    const float* b3  = (const float*)d_in[6];
    const float* Wih = (const float*)d_in[7];
    const float* Whh = (const float*)d_in[8];
    const float* bih = (const float*)d_in[9];
    const float* bhh = (const float*)d_in[10];
    const float* Wo  = (const float*)d_in[11];
    const float* bo  = (const float*)d_in[12];
    float* out = (float*)d_out;

    const int smem = 52224 * 4;  // 208896 B
    cudaFuncSetAttribute(fused_kernel, cudaFuncAttributeMaxDynamicSharedMemorySize, smem);

    prep_kernel<<<288, 256>>>(W1, W2, W3, Whh);
    fused_kernel<<<BS / 128, 512, smem>>>(z, b1, b2, b3, Wih, bih, bhh, Wo, bo, out);
}

// round 14
// speedup vs baseline: 1.5533x; 1.0605x over previous
#include <cuda_runtime.h>
#include <cuda_bf16.h>

#define BS 131072
#define PLEN 10
#define NCH1 23   // GEMM1: K=361 padded to 368 = 23 chunks of 16

// -------- pre-split weights: packed bf16 (2 per u32 along k), hi & lo, natural order.
// g_Whh holds 208 rows: 0-191 = Whh rows PERMUTED gate-interleaved per 48-row warp
// slice ([r x16 | z x16 | n x16] of the same 16 units), 192-193 = Wo, 194-207 = zero.
__device__ __align__(16) unsigned g_W1h[NCH1 * 256 * 8], g_W1l[NCH1 * 256 * 8]; // [kc][n][8]
__device__ __align__(16) unsigned g_W2h[4 * 128 * 32],   g_W2l[4 * 128 * 32];   // [kc][n][32]
__device__ __align__(16) unsigned g_W3h[64 * 64],        g_W3l[64 * 64];        // [n][64]
__device__ __align__(16) unsigned g_Whh[208 * 32],       g_Whl[208 * 32];       // [n][32]

// ---------------------------------------------------------------------------
__device__ __forceinline__ unsigned packbf(float lo, float hi) {
    unsigned r;
    asm("cvt.rn.bf16x2.f32 %0, %1, %2;" : "=r"(r) : "f"(hi), "f"(lo));
    return r;
}
__device__ __forceinline__ void split2(float v0, float v1, unsigned& hi, unsigned& lo) {
    hi = packbf(v0, v1);
    float h0 = __uint_as_float(hi << 16);
    float h1 = __uint_as_float(hi & 0xffff0000u);
    lo = packbf(v0 - h0, v1 - h1);
}
__device__ __forceinline__ float bflo(unsigned u) { return __uint_as_float(u << 16); }
__device__ __forceinline__ float bfhi(unsigned u) { return __uint_as_float(u & 0xffff0000u); }
__device__ __forceinline__ float relu_(float v) { return v > 0.f ? v : 0.f; }
__device__ __forceinline__ float tanhapx(float x) {
    float y; asm("tanh.approx.f32 %0, %1;" : "=f"(y) : "f"(x)); return y;
}

__device__ __forceinline__ void mma16(float* c, const unsigned* a, unsigned b0, unsigned b1) {
    asm("mma.sync.aligned.m16n8k16.row.col.f32.bf16.bf16.f32 "
        "{%0,%1,%2,%3},{%4,%5,%6,%7},{%8,%9},{%0,%1,%2,%3};"
        : "+f"(c[0]), "+f"(c[1]), "+f"(c[2]), "+f"(c[3])
        : "r"(a[0]), "r"(a[1]), "r"(a[2]), "r"(a[3]), "r"(b0), "r"(b1));
}

__device__ __forceinline__ void ldsm4(unsigned& r0, unsigned& r1, unsigned& r2, unsigned& r3,
                                      unsigned addr) {
    asm volatile("ldmatrix.sync.aligned.m8n8.x4.shared.b16 {%0,%1,%2,%3}, [%4];"
        : "=r"(r0), "=r"(r1), "=r"(r2), "=r"(r3) : "r"(addr));
}

__device__ __forceinline__ void cpa4(void* s, const void* g) {
    unsigned a = (unsigned)__cvta_generic_to_shared(s);
    asm volatile("cp.async.ca.shared.global [%0],[%1],4;" :: "r"(a), "l"(g) : "memory");
}
__device__ __forceinline__ void cpa16(void* s, const void* g) {
    unsigned a = (unsigned)__cvta_generic_to_shared(s);
    asm volatile("cp.async.cg.shared.global [%0],[%1],16;" :: "r"(a), "l"(g) : "memory");
}
__device__ __forceinline__ void cp_commit() { asm volatile("cp.async.commit_group;" ::: "memory"); }
template <int N>
__device__ __forceinline__ void cp_wait() { asm volatile("cp.async.wait_group %0;" :: "n"(N) : "memory"); }

// load fp32 A tile fragment (16 rows) and split to bf16 hi/lo frags (GEMM1 z only)
__device__ __forceinline__ void ldA_f32(const float* base, int stride, int g, int tg,
                                        unsigned* Ah, unsigned* Al) {
    float2 p0 = *(const float2*)(base + g * stride + 2 * tg);
    float2 p1 = *(const float2*)(base + (g + 8) * stride + 2 * tg);
    float2 p2 = *(const float2*)(base + g * stride + 2 * tg + 8);
    float2 p3 = *(const float2*)(base + (g + 8) * stride + 2 * tg + 8);
    split2(p0.x, p0.y, Ah[0], Al[0]);
    split2(p1.x, p1.y, Ah[1], Al[1]);
    split2(p2.x, p2.y, Ah[2], Al[2]);
    split2(p3.x, p3.y, Ah[3], Al[3]);
}

// 12-mma group, dependency distance 4; per-acc order (hh, hl, lh) preserved
#define MMA12(A0h, A1h, A0l, A1l, BH, BL, C0, C1)          \
    do {                                                    \
        mma16(C0, A0h, BH[0], BH[1]);                       \
        mma16(C1, A1h, BH[0], BH[1]);                       \
        mma16((C0) + 4, A0h, BH[2], BH[3]);                 \
        mma16((C1) + 4, A1h, BH[2], BH[3]);                 \
        mma16(C0, A0h, BL[0], BL[1]);                       \
        mma16(C1, A1h, BL[0], BL[1]);                       \
        mma16((C0) + 4, A0h, BL[2], BL[3]);                 \
        mma16((C1) + 4, A1h, BL[2], BL[3]);                 \
        mma16(C0, A0l, BH[0], BH[1]);                       \
        mma16(C1, A1l, BH[0], BH[1]);                       \
        mma16((C0) + 4, A0l, BH[2], BH[3]);                 \
        mma16((C1) + 4, A1l, BH[2], BH[3]);                 \
    } while (0)

// ---------------------------------------------------------------------------
// prep: elems = 47104 + 16384 + 4096 + 6656 = 74240 = 290 * 256
// ---------------------------------------------------------------------------
__global__ void prep_kernel(const float* __restrict__ W1, const float* __restrict__ W2,
                            const float* __restrict__ W3, const float* __restrict__ Whh,
                            const float* __restrict__ Wo) {
    int i = blockIdx.x * 256 + threadIdx.x;
    const int N1 = NCH1 * 256 * 8, N2 = 4 * 128 * 32, N3 = 64 * 64, N4 = 208 * 32;
    if (i < N1) {
        int kc = i >> 11, rem = i & 2047, n = rem >> 3, u = rem & 7;
        int k = kc * 16 + 2 * u;
        float v0 = (k < 361)     ? W1[n * 361 + k]     : 0.f;
        float v1 = (k + 1 < 361) ? W1[n * 361 + k + 1] : 0.f;
        split2(v0, v1, g_W1h[i], g_W1l[i]);
    } else if (i < N1 + N2) {
        int j = i - N1;
        int kc = j >> 12, rem = j & 4095, n = rem >> 5, u = rem & 31;
        int k = kc * 64 + 2 * u;
        split2(W2[n * 256 + k], W2[n * 256 + k + 1], g_W2h[j], g_W2l[j]);
    } else if (i < N1 + N2 + N3) {
        int j = i - N1 - N2;
        int n = j >> 6, u = j & 63;
        split2(W3[n * 128 + 2 * u], W3[n * 128 + 2 * u + 1], g_W3h[j], g_W3l[j]);
    } else if (i < N1 + N2 + N3 + N4) {
        int j = i - N1 - N2 - N3;
        int nn = j >> 5, u = j & 31, k = 2 * u;
        unsigned hi = 0, lo = 0;
        if (nn < 192) {
            int wnx = nn / 48, l = nn % 48, gate = l >> 4, jj = l & 15;
            int orig = gate * 64 + wnx * 16 + jj;
            split2(Whh[orig * 64 + k], Whh[orig * 64 + k + 1], hi, lo);
        } else if (nn < 194) {
            int o = nn - 192;
            split2(Wo[o * 64 + k], Wo[o * 64 + k + 1], hi, lo);
        }
        g_Whh[j] = hi; g_Whl[j] = lo;
    }
}

// ---------------------------------------------------------------------------
// fused kernel. MLP identical to the 801us kernel. GRU: in-register gates via
// gate-interleaved Whh permutation + Wo folded into the mma (no gh buffer).
// GRU smem (u32): hhi [128][36] @0, hlo @4608, whhh [208][36] @9216, whhl @16704,
//   wih @24192(384), sbrz @24576(128), sbin @24704(64), sbhn @24768(64),
//   swo @24832(128), sbo @24960, x @24964(256), xh [128][20] @25220 (..27780)
// ---------------------------------------------------------------------------
__global__ void __launch_bounds__(512, 1) fused_kernel(
    const float* __restrict__ z,
    const float* __restrict__ b1, const float* __restrict__ b2, const float* __restrict__ b3,
    const float* __restrict__ Wih, const float* __restrict__ bih, const float* __restrict__ bhh,
    const float* __restrict__ Wo, const float* __restrict__ bo,
    float* __restrict__ out)
{
    extern __shared__ float sm[];
    unsigned* smu = (unsigned*)sm;
    const unsigned sb = (unsigned)__cvta_generic_to_shared(sm);

    const int tid = threadIdx.x, lane = tid & 31, wid = tid >> 5;
    const int g = lane >> 2, tg = lane & 3;
    const int wm = wid & 3, wn = wid >> 2;
    const int m0 = blockIdx.x * 128;

    const int arow = lane & 15;
    const int ak4  = (lane >> 4) * 4;
    const int brow = ((lane >> 4) << 3) + (lane & 7);
    const int bk4  = ((lane >> 3) & 1) * 4;

    unsigned* h1hi = smu;            // [128][132]
    unsigned* h1lo = smu + 16896;
    float*    zbuf = sm + 33792;     // 2 x [128][20]

    // ================= GEMM1: h1 = relu(z @ W1^T + b1) =================
    float acc1[2][8][4];
    #pragma unroll
    for (int a = 0; a < 2; a++)
        #pragma unroll
        for (int b = 0; b < 8; b++)
            #pragma unroll
            for (int c = 0; c < 4; c++) acc1[a][b][c] = 0.f;

    auto stage1 = [&](int buf, int kc) {
        const int k0 = kc * 16;
        {
            int m = tid >> 2, q4 = (tid & 3) * 4;
            int gk = k0 + q4;
            float* dst = zbuf + buf * 2560 + m * 20 + q4;
            const float* src = z + (size_t)(m0 + m) * 361 + gk;
            #pragma unroll
            for (int j = 0; j < 4; j++) {
                if (gk + j < 361) cpa4(dst + j, src + j);
                else              dst[j] = 0.f;
            }
        }
        {
            int n = tid >> 1, q4 = (tid & 1) * 4;
            cpa16(smu + 38912 + buf * 3072 + n * 12 + q4, g_W1h + kc * 2048 + n * 8 + q4);
            cpa16(smu + 45056 + buf * 3072 + n * 12 + q4, g_W1l + kc * 2048 + n * 8 + q4);
        }
    };

    const int w1_frag = (wn * 64 + brow) * 12 + bk4;

    stage1(0, 0); cp_commit();
    for (int kc = 0; kc < NCH1; kc++) {
        if (kc + 1 < NCH1) { stage1((kc + 1) & 1, kc + 1); cp_commit(); cp_wait<1>(); }
        else               { cp_wait<0>(); }
        __syncthreads();
        const float* az = zbuf + (kc & 1) * 2560 + (wm * 32) * 20;
        unsigned bh_addr = sb + 4u * (38912 + (kc & 1) * 3072 + w1_frag);
        unsigned bl_addr = bh_addr + 4u * 6144;
        unsigned Ah[2][4], Al[2][4];
        ldA_f32(az,           20, g, tg, Ah[0], Al[0]);
        ldA_f32(az + 16 * 20, 20, g, tg, Ah[1], Al[1]);
        #pragma unroll
        for (int p = 0; p < 4; p++) {
            unsigned bh[4], bl[4];
            ldsm4(bh[0], bh[1], bh[2], bh[3], bh_addr + 4u * (p * 16 * 12));
            ldsm4(bl[0], bl[1], bl[2], bl[3], bl_addr + 4u * (p * 16 * 12));
            MMA12(Ah[0], Ah[1], Al[0], Al[1], bh, bl, acc1[0][2*p], acc1[1][2*p]);
        }
        __syncthreads();
    }

    // prefetch W2 chunk 0
    auto stage2 = [&](int buf, int kc) {
        #pragma unroll
        for (int i = tid; i < 1024; i += 512) {
            int n = i >> 3, q4 = (i & 7) * 4;
            cpa16(smu + 33792 + buf * 4608 + n * 36 + q4, g_W2h + kc * 4096 + n * 32 + q4);
            cpa16(smu + 43008 + buf * 4608 + n * 36 + q4, g_W2l + kc * 4096 + n * 32 + q4);
        }
    };
    stage2(0, 0); cp_commit();

    // GEMM1 epilogue -> packed h1
    #pragma unroll
    for (int mt = 0; mt < 2; mt++) {
        #pragma unroll
        for (int nt = 0; nt < 8; nt++) {
            int m = wm * 32 + mt * 16 + g;
            int n = wn * 64 + nt * 8 + 2 * tg;
            int nu = n >> 1;
            float bv0 = __ldg(b1 + n), bv1 = __ldg(b1 + n + 1);
            unsigned hi, lo;
            split2(relu_(acc1[mt][nt][0] + bv0), relu_(acc1[mt][nt][1] + bv1), hi, lo);
            h1hi[m * 132 + nu] = hi; h1lo[m * 132 + nu] = lo;
            split2(relu_(acc1[mt][nt][2] + bv0), relu_(acc1[mt][nt][3] + bv1), hi, lo);
            h1hi[(m + 8) * 132 + nu] = hi; h1lo[(m + 8) * 132 + nu] = lo;
        }
    }
    __syncthreads();

    // ================= GEMM2 =================
    float acc2[2][4][4];
    #pragma unroll
    for (int a = 0; a < 2; a++)
        #pragma unroll
        for (int b = 0; b < 4; b++)
            #pragma unroll
            for (int c = 0; c < 4; c++) acc2[a][b][c] = 0.f;

    const int h1_fragA = (wm * 32 + arow) * 132 + ak4;
    const int w2_fragB = (wn * 32 + brow) * 36 + bk4;

    for (int kc = 0; kc < 4; kc++) {
        if (kc + 1 < 4) { stage2((kc + 1) & 1, kc + 1); cp_commit(); cp_wait<1>(); }
        else            { cp_wait<0>(); }
        __syncthreads();
        unsigned w2h_addr = sb + 4u * (33792 + (kc & 1) * 4608 + w2_fragB);
        unsigned w2l_addr = w2h_addr + 4u * 9216;
        #pragma unroll
        for (int q = 0; q < 4; q++) {
            int u0 = kc * 32 + q * 8;
            unsigned Ah[2][4], Al[2][4];
            ldsm4(Ah[0][0], Ah[0][1], Ah[0][2], Ah[0][3], sb + 4u * (h1_fragA + u0));
            ldsm4(Ah[1][0], Ah[1][1], Ah[1][2], Ah[1][3], sb + 4u * (h1_fragA + 16 * 132 + u0));
            ldsm4(Al[0][0], Al[0][1], Al[0][2], Al[0][3], sb + 4u * (16896 + h1_fragA + u0));
            ldsm4(Al[1][0], Al[1][1], Al[1][2], Al[1][3], sb + 4u * (16896 + h1_fragA + 16 * 132 + u0));
            #pragma unroll
            for (int p = 0; p < 2; p++) {
                unsigned bh[4], bl[4];
                ldsm4(bh[0], bh[1], bh[2], bh[3], w2h_addr + 4u * (p * 16 * 36 + q * 8));
                ldsm4(bl[0], bl[1], bl[2], bl[3], w2l_addr + 4u * (p * 16 * 36 + q * 8));
                MMA12(Ah[0], Ah[1], Al[0], Al[1], bh, bl, acc2[0][2*p], acc2[1][2*p]);
            }
        }
        __syncthreads();
    }

    // ---- stage W3 @8704/13056 + h2 epilogue @33792 ----
    unsigned* w3h = smu + 8704;   // [64][68]
    unsigned* w3l = smu + 13056;
    #pragma unroll
    for (int i = tid; i < 2048; i += 512) {
        int half = i >> 10, j = i & 1023;
        int n = j >> 4, q4 = (j & 15) * 4;
        cpa16((half ? w3l : w3h) + n * 68 + q4, (half ? g_W3l : g_W3h) + n * 64 + q4);
    }
    cp_commit();

    unsigned* h2hi = smu + 33792;  // [128][68]
    unsigned* h2lo = smu + 42496;
    #pragma unroll
    for (int mt = 0; mt < 2; mt++) {
        #pragma unroll
        for (int nt = 0; nt < 4; nt++) {
            int m = wm * 32 + mt * 16 + g;
            int n = wn * 32 + nt * 8 + 2 * tg;
            int nu = n >> 1;
            float bv0 = __ldg(b2 + n), bv1 = __ldg(b2 + n + 1);
            unsigned hi, lo;
            split2(relu_(acc2[mt][nt][0] + bv0), relu_(acc2[mt][nt][1] + bv1), hi, lo);
            h2hi[m * 68 + nu] = hi; h2lo[m * 68 + nu] = lo;
            split2(relu_(acc2[mt][nt][2] + bv0), relu_(acc2[mt][nt][3] + bv1), hi, lo);
            h2hi[(m + 8) * 68 + nu] = hi; h2lo[(m + 8) * 68 + nu] = lo;
        }
    }
    cp_wait<0>();
    __syncthreads();

    // ================= GEMM3 =================
    float acc3[2][2][4];
    #pragma unroll
    for (int a = 0; a < 2; a++)
        #pragma unroll
        for (int b = 0; b < 2; b++)
            #pragma unroll
            for (int c = 0; c < 4; c++) acc3[a][b][c] = 0.f;

    const int h2_fragA = 33792 + (wm * 32 + arow) * 68 + ak4;
    const int w3_fragB = 8704 + (wn * 16 + brow) * 68 + bk4;

    #pragma unroll
    for (int q = 0; q < 8; q++) {
        int u0 = q * 8;
        unsigned Ah[2][4], Al[2][4];
        ldsm4(Ah[0][0], Ah[0][1], Ah[0][2], Ah[0][3], sb + 4u * (h2_fragA + u0));
        ldsm4(Ah[1][0], Ah[1][1], Ah[1][2], Ah[1][3], sb + 4u * (h2_fragA + 16 * 68 + u0));
        ldsm4(Al[0][0], Al[0][1], Al[0][2], Al[0][3], sb + 4u * (8704 + h2_fragA + u0));
        ldsm4(Al[1][0], Al[1][1], Al[1][2], Al[1][3], sb + 4u * (8704 + h2_fragA + 16 * 68 + u0));
        unsigned bh[4], bl[4];
        ldsm4(bh[0], bh[1], bh[2], bh[3], sb + 4u * (w3_fragB + u0));
        ldsm4(bl[0], bl[1], bl[2], bl[3], sb + 4u * (4352 + w3_fragB + u0));
        MMA12(Ah[0], Ah[1], Al[0], Al[1], bh, bl, acc3[0][0], acc3[1][0]);
    }
    __syncthreads();   // all w3/h2 reads done before overwrite

    // ================= GRU setup =================
    unsigned* hhi  = smu;            // [128][36]
    unsigned* hlo  = smu + 4608;
    unsigned* whhh = smu + 9216;     // [208][36]
    unsigned* whhl = smu + 16704;
    float*    wih  = sm + 24192;     // [192][2]
    float*    sbrz = sm + 24576;     // [128]
    float*    sbin = sm + 24704;     // [64]
    float*    sbhn = sm + 24768;     // [64]
    float*    swo  = sm + 24832;     // [128]
    float*    sbo  = sm + 24960;     // [2]
    float*    x    = sm + 24964;     // [128][2]
    float*    xh   = sm + 25220;     // [128][20]

    #pragma unroll
    for (int i = tid; i < 3328; i += 512) {
        int half = (i >= 1664), j = half ? i - 1664 : i;
        int n = j >> 3, q4 = (j & 7) * 4;
        cpa16((half ? whhl : whhh) + n * 36 + q4, (half ? g_Whl : g_Whh) + n * 32 + q4);
    }
    cp_commit();
    if (tid < 384) wih[tid] = Wih[tid];
    if (tid < 128) sbrz[tid] = bih[tid] + bhh[tid];
    if (tid >= 128 && tid < 192) { sbin[tid - 128] = bih[tid]; sbhn[tid - 128] = bhh[tid]; }
    if (tid >= 192 && tid < 320) swo[tid - 192] = Wo[tid - 192];
    if (tid >= 320 && tid < 322) sbo[tid - 320] = bo[tid - 320];
    if (tid < 256) x[tid] = 0.f;

    // GEMM3 epilogue -> packed h
    #pragma unroll
    for (int mt = 0; mt < 2; mt++) {
        #pragma unroll
        for (int nt = 0; nt < 2; nt++) {
            int m = wm * 32 + mt * 16 + g;
            int n = wn * 16 + nt * 8 + 2 * tg;
            int nu = n >> 1;
            float bv0 = __ldg(b3 + n), bv1 = __ldg(b3 + n + 1);
            unsigned hi, lo;
            split2(relu_(acc3[mt][nt][0] + bv0), relu_(acc3[mt][nt][1] + bv1), hi, lo);
            hhi[m * 36 + nu] = hi; hlo[m * 36 + nu] = lo;
            split2(relu_(acc3[mt][nt][2] + bv0), relu_(acc3[mt][nt][3] + bv1), hi, lo);
            hhi[(m + 8) * 36 + nu] = hi; hlo[(m + 8) * 36 + nu] = lo;
        }
    }
    cp_wait<0>();
    __syncthreads();

    // ================= GRU loop: in-register gates =================
    const int h_fragA   = (wm * 32 + arow) * 36 + ak4;
    const int whh_fragB = 9216 + (wn * 48 + brow) * 36 + bk4;
    const int dx_fragB  = 9216 + (192 + brow) * 36 + bk4;
    const float4* wih4  = (const float4*)wih;
    const float2* sbrz2 = (const float2*)sbrz;
    const float2* sbin2 = (const float2*)sbin;
    const float2* sbhn2 = (const float2*)sbhn;

    for (int t = 0; t < PLEN; t++) {
        float acc[2][6][4];
        float accD[2][4];
        #pragma unroll
        for (int a = 0; a < 2; a++) {
            #pragma unroll
            for (int b = 0; b < 6; b++)
                #pragma unroll
                for (int c = 0; c < 4; c++) acc[a][b][c] = 0.f;
            #pragma unroll
            for (int c = 0; c < 4; c++) accD[a][c] = 0.f;
        }

        #pragma unroll
        for (int q = 0; q < 4; q++) {
            unsigned Ah[2][4], Al[2][4];
            ldsm4(Ah[0][0], Ah[0][1], Ah[0][2], Ah[0][3], sb + 4u * (h_fragA + q * 8));
            ldsm4(Ah[1][0], Ah[1][1], Ah[1][2], Ah[1][3], sb + 4u * (h_fragA + 16 * 36 + q * 8));
            ldsm4(Al[0][0], Al[0][1], Al[0][2], Al[0][3], sb + 4u * (4608 + h_fragA + q * 8));
            ldsm4(Al[1][0], Al[1][1], Al[1][2], Al[1][3], sb + 4u * (4608 + h_fragA + 16 * 36 + q * 8));
            #pragma unroll
            for (int p = 0; p < 3; p++) {
                unsigned bh[4], bl[4];
                ldsm4(bh[0], bh[1], bh[2], bh[3], sb + 4u * (whh_fragB + p * 16 * 36 + q * 8));
                ldsm4(bl[0], bl[1], bl[2], bl[3], sb + 4u * (7488 + whh_fragB + p * 16 * 36 + q * 8));
                MMA12(Ah[0], Ah[1], Al[0], Al[1], bh, bl, acc[0][2*p], acc[1][2*p]);
            }
            if (wn == 3) {  // dx tile (Wo rows 192-193; 194-207 zero)
                unsigned dh[4], dl[4];
                ldsm4(dh[0], dh[1], dh[2], dh[3], sb + 4u * (dx_fragB + q * 8));
                ldsm4(dl[0], dl[1], dl[2], dl[3], sb + 4u * (7488 + dx_fragB + q * 8));
                mma16(accD[0], Ah[0], dh[0], dh[1]);
                mma16(accD[1], Ah[1], dh[0], dh[1]);
                mma16(accD[0], Ah[0], dl[0], dl[1]);
                mma16(accD[1], Ah[1], dl[0], dl[1]);
                mma16(accD[0], Al[0], dh[0], dh[1]);
                mma16(accD[1], Al[1], dh[0], dh[1]);
            }
        }
        // x_{t-1} = x_{t-2} + h_{t-1}@Wo + bo  (cols 192,193 held by tg==0 lanes)
        if (t > 0 && wn == 3 && tg == 0) {
            float so0 = sbo[0], so1 = sbo[1];
            #pragma unroll
            for (int mt = 0; mt < 2; mt++) {
                #pragma unroll
                for (int sel = 0; sel < 2; sel++) {
                    int row = wm * 32 + mt * 16 + g + sel * 8;
                    float xv0 = x[2 * row]     + accD[mt][sel * 2]     + so0;
                    float xv1 = x[2 * row + 1] + accD[mt][sel * 2 + 1] + so1;
                    x[2 * row] = xv0; x[2 * row + 1] = xv1;
                    xh[row * 20 + (t - 1) * 2]     = xv0;
                    xh[row * 20 + (t - 1) * 2 + 1] = xv1;
                }
            }
        }
        __syncthreads();

        // gates from registers; h updated in place (thread owns its elements)
        #pragma unroll
        for (int mt = 0; mt < 2; mt++) {
            int r0 = wm * 32 + mt * 16 + g;
            #pragma unroll
            for (int b = 0; b < 2; b++) {
                int q = wn * 8 + b * 4 + tg;
                float4 wr = wih4[q], wz = wih4[32 + q], wnv = wih4[64 + q];
                float2 br = sbrz2[q], bz = sbrz2[32 + q];
                float2 bi = sbin2[q], bh2 = sbhn2[q];
                #pragma unroll
                for (int sel = 0; sel < 2; sel++) {
                    int row = r0 + sel * 8;
                    int ai = sel * 2;
                    float xv0 = x[2 * row], xv1 = x[2 * row + 1];
                    float rg0 = 0.5f * tanhapx(0.5f * (acc[mt][b][ai]     + xv0 * wr.x + xv1 * wr.y + br.x)) + 0.5f;
                    float rg1 = 0.5f * tanhapx(0.5f * (acc[mt][b][ai + 1] + xv0 * wr.z + xv1 * wr.w + br.y)) + 0.5f;
                    float zg0 = 0.5f * tanhapx(0.5f * (acc[mt][2 + b][ai]     + xv0 * wz.x + xv1 * wz.y + bz.x)) + 0.5f;
                    float zg1 = 0.5f * tanhapx(0.5f * (acc[mt][2 + b][ai + 1] + xv0 * wz.z + xv1 * wz.w + bz.y)) + 0.5f;
                    float ng0 = tanhapx(xv0 * wnv.x + xv1 * wnv.y + bi.x + rg0 * (acc[mt][4 + b][ai]     + bh2.x));
                    float ng1 = tanhapx(xv0 * wnv.z + xv1 * wnv.w + bi.y + rg1 * (acc[mt][4 + b][ai + 1] + bh2.y));
                    unsigned uh = hhi[row * 36 + q], ul = hlo[row * 36 + q];
                    float h0 = bflo(uh) + bflo(ul);
                    float h1 = bfhi(uh) + bfhi(ul);
                    float hn0 = (1.f - zg0) * ng0 + zg0 * h0;
                    float hn1 = (1.f - zg1) * ng1 + zg1 * h1;
                    unsigned nh, nl;
                    split2(hn0, hn1, nh, nl);
                    hhi[row * 36 + q] = nh; hlo[row * 36 + q] = nl;
                }
            }
        }
        __syncthreads();
    }

    // final Wo (step PLEN-1)
    if (tid < 256) {
        int r = tid >> 1, o = tid & 1;
        float s = sbo[o];
        const float* wr = swo + o * 64;
        #pragma unroll 8
        for (int c = 0; c < 32; c++) {
            unsigned uh = hhi[r * 36 + c], ul = hlo[r * 36 + c];
            s += (bflo(uh) + bflo(ul)) * wr[2 * c];
            s += (bfhi(uh) + bfhi(ul)) * wr[2 * c + 1];
        }
        float xv = x[r * 2 + o] + s;
        xh[r * 20 + (PLEN - 1) * 2 + o] = xv;
    }
    __syncthreads();

    // coalesced output: out[b, t, o]
    #pragma unroll
    for (int i = tid; i < 640; i += 512) {
        int r = i / 5, q = (i % 5) * 4;
        *(float4*)&out[(size_t)(m0 + r) * 20 + q] = *(const float4*)&xh[r * 20 + q];
    }
}

// ---------------------------------------------------------------------------
extern "C" void kernel_launch(void* const* d_in, const int* in_sizes, int n_in,
                              void* d_out, int out_size)
{
    const float* z   = (const float*)d_in[0];
    const float* W1  = (const float*)d_in[1];
    const float* b1  = (const float*)d_in[2];
    const float* W2  = (const float*)d_in[3];
    const float* b2  = (const float*)d_in[4];
    const float* W3  = (const float*)d_in[5];
    const float* b3  = (const float*)d_in[6];
    const float* Wih = (const float*)d_in[7];
    const float* Whh = (const float*)d_in[8];
    const float* bih = (const float*)d_in[9];
    const float* bhh = (const float*)d_in[10];
    const float* Wo  = (const float*)d_in[11];
    const float* bo  = (const float*)d_in[12];
    float* out = (float*)d_out;

    const int smem = 52224 * 4;  // 208896 B
    cudaFuncSetAttribute(fused_kernel, cudaFuncAttributeMaxDynamicSharedMemorySize, smem);

    prep_kernel<<<290, 256>>>(W1, W2, W3, Whh, Wo);
    fused_kernel<<<BS / 128, 512, smem>>>(z, b1, b2, b3, Wih, bih, bhh, Wo, bo, out);
}

// round 15
// speedup vs baseline: 1.6884x; 1.0870x over previous
#include <cuda_runtime.h>
#include <cuda_bf16.h>

#define BS 131072
#define PLEN 10
#define NCH1 23   // GEMM1: K=361 padded to 368 = 23 chunks of 16

// -------- pre-split weights: packed bf16 (2 per u32 along k), hi & lo, natural order.
// g_Whh holds 208 rows: 0-191 = Whh rows PERMUTED gate-interleaved per 48-row warp
// slice ([r x16 | z x16 | n x16] of the same 16 units), 192-193 = Wo, 194-207 = zero.
__device__ __align__(16) unsigned g_W1h[NCH1 * 256 * 8], g_W1l[NCH1 * 256 * 8]; // [kc][n][8]
__device__ __align__(16) unsigned g_W2h[4 * 128 * 32],   g_W2l[4 * 128 * 32];   // [kc][n][32]
__device__ __align__(16) unsigned g_W3h[64 * 64],        g_W3l[64 * 64];        // [n][64]
__device__ __align__(16) unsigned g_Whh[208 * 32],       g_Whl[208 * 32];       // [n][32]

// ---------------------------------------------------------------------------
__device__ __forceinline__ unsigned packbf(float lo, float hi) {
    unsigned r;
    asm("cvt.rn.bf16x2.f32 %0, %1, %2;" : "=r"(r) : "f"(hi), "f"(lo));
    return r;
}
__device__ __forceinline__ void split2(float v0, float v1, unsigned& hi, unsigned& lo) {
    hi = packbf(v0, v1);
    float h0 = __uint_as_float(hi << 16);
    float h1 = __uint_as_float(hi & 0xffff0000u);
    lo = packbf(v0 - h0, v1 - h1);
}
__device__ __forceinline__ float bflo(unsigned u) { return __uint_as_float(u << 16); }
__device__ __forceinline__ float bfhi(unsigned u) { return __uint_as_float(u & 0xffff0000u); }
__device__ __forceinline__ float relu_(float v) { return v > 0.f ? v : 0.f; }
__device__ __forceinline__ float tanhapx(float x) {
    float y; asm("tanh.approx.f32 %0, %1;" : "=f"(y) : "f"(x)); return y;
}

__device__ __forceinline__ void mma16(float* c, const unsigned* a, unsigned b0, unsigned b1) {
    asm("mma.sync.aligned.m16n8k16.row.col.f32.bf16.bf16.f32 "
        "{%0,%1,%2,%3},{%4,%5,%6,%7},{%8,%9},{%0,%1,%2,%3};"
        : "+f"(c[0]), "+f"(c[1]), "+f"(c[2]), "+f"(c[3])
        : "r"(a[0]), "r"(a[1]), "r"(a[2]), "r"(a[3]), "r"(b0), "r"(b1));
}

__device__ __forceinline__ void ldsm4(unsigned& r0, unsigned& r1, unsigned& r2, unsigned& r3,
                                      unsigned addr) {
    asm volatile("ldmatrix.sync.aligned.m8n8.x4.shared.b16 {%0,%1,%2,%3}, [%4];"
        : "=r"(r0), "=r"(r1), "=r"(r2), "=r"(r3) : "r"(addr));
}

__device__ __forceinline__ void cpa16(void* s, const void* g) {
    unsigned a = (unsigned)__cvta_generic_to_shared(s);
    asm volatile("cp.async.cg.shared.global [%0],[%1],16;" :: "r"(a), "l"(g) : "memory");
}
__device__ __forceinline__ void cp_commit() { asm volatile("cp.async.commit_group;" ::: "memory"); }
template <int N>
__device__ __forceinline__ void cp_wait() { asm volatile("cp.async.wait_group %0;" :: "n"(N) : "memory"); }

// 12-mma group, dependency distance 4; per-acc order (hh, hl, lh) preserved
#define MMA12(A0h, A1h, A0l, A1l, BH, BL, C0, C1)          \
    do {                                                    \
        mma16(C0, A0h, BH[0], BH[1]);                       \
        mma16(C1, A1h, BH[0], BH[1]);                       \
        mma16((C0) + 4, A0h, BH[2], BH[3]);                 \
        mma16((C1) + 4, A1h, BH[2], BH[3]);                 \
        mma16(C0, A0h, BL[0], BL[1]);                       \
        mma16(C1, A1h, BL[0], BL[1]);                       \
        mma16((C0) + 4, A0h, BL[2], BL[3]);                 \
        mma16((C1) + 4, A1h, BL[2], BL[3]);                 \
        mma16(C0, A0l, BH[0], BH[1]);                       \
        mma16(C1, A1l, BH[0], BH[1]);                       \
        mma16((C0) + 4, A0l, BH[2], BH[3]);                 \
        mma16((C1) + 4, A1l, BH[2], BH[3]);                 \
    } while (0)

// ---------------------------------------------------------------------------
// prep: elems = 47104 + 16384 + 4096 + 6656 = 74240 = 290 * 256
// ---------------------------------------------------------------------------
__global__ void prep_kernel(const float* __restrict__ W1, const float* __restrict__ W2,
                            const float* __restrict__ W3, const float* __restrict__ Whh,
                            const float* __restrict__ Wo) {
    int i = blockIdx.x * 256 + threadIdx.x;
    const int N1 = NCH1 * 256 * 8, N2 = 4 * 128 * 32, N3 = 64 * 64, N4 = 208 * 32;
    if (i < N1) {
        int kc = i >> 11, rem = i & 2047, n = rem >> 3, u = rem & 7;
        int k = kc * 16 + 2 * u;
        float v0 = (k < 361)     ? W1[n * 361 + k]     : 0.f;
        float v1 = (k + 1 < 361) ? W1[n * 361 + k + 1] : 0.f;
        split2(v0, v1, g_W1h[i], g_W1l[i]);
    } else if (i < N1 + N2) {
        int j = i - N1;
        int kc = j >> 12, rem = j & 4095, n = rem >> 5, u = rem & 31;
        int k = kc * 64 + 2 * u;
        split2(W2[n * 256 + k], W2[n * 256 + k + 1], g_W2h[j], g_W2l[j]);
    } else if (i < N1 + N2 + N3) {
        int j = i - N1 - N2;
        int n = j >> 6, u = j & 63;
        split2(W3[n * 128 + 2 * u], W3[n * 128 + 2 * u + 1], g_W3h[j], g_W3l[j]);
    } else if (i < N1 + N2 + N3 + N4) {
        int j = i - N1 - N2 - N3;
        int nn = j >> 5, u = j & 31, k = 2 * u;
        unsigned hi = 0, lo = 0;
        if (nn < 192) {
            int wnx = nn / 48, l = nn % 48, gate = l >> 4, jj = l & 15;
            int orig = gate * 64 + wnx * 16 + jj;
            split2(Whh[orig * 64 + k], Whh[orig * 64 + k + 1], hi, lo);
        } else if (nn < 194) {
            int o = nn - 192;
            split2(Wo[o * 64 + k], Wo[o * 64 + k + 1], hi, lo);
        }
        g_Whh[j] = hi; g_Whl[j] = lo;
    }
}

// ---------------------------------------------------------------------------
// fused kernel. GEMM1 now splits z at staging (register LDG prefetch + packed
// bf16 STS) and loads A via ldmatrix — bit-identical numerics to the 755us
// kernel. GEMM2/3 + GRU unchanged.
// P1 smem (u32): h1hi [128][132] @0, h1lo @16896;
//   zh 2x[128][12] @33792(+1536), zl @36864(+1536),
//   w1h 2x[256][12] @39936, w1l @46080 (..52224 exactly)
// ---------------------------------------------------------------------------
__global__ void __launch_bounds__(512, 1) fused_kernel(
    const float* __restrict__ z,
    const float* __restrict__ b1, const float* __restrict__ b2, const float* __restrict__ b3,
    const float* __restrict__ Wih, const float* __restrict__ bih, const float* __restrict__ bhh,
    const float* __restrict__ Wo, const float* __restrict__ bo,
    float* __restrict__ out)
{
    extern __shared__ float sm[];
    unsigned* smu = (unsigned*)sm;
    const unsigned sb = (unsigned)__cvta_generic_to_shared(sm);

    const int tid = threadIdx.x, lane = tid & 31, wid = tid >> 5;
    const int g = lane >> 2, tg = lane & 3;
    const int wm = wid & 3, wn = wid >> 2;
    const int m0 = blockIdx.x * 128;

    const int arow = lane & 15;
    const int ak4  = (lane >> 4) * 4;
    const int brow = ((lane >> 4) << 3) + (lane & 7);
    const int bk4  = ((lane >> 3) & 1) * 4;

    unsigned* h1hi = smu;            // [128][132]
    unsigned* h1lo = smu + 16896;

    // ================= GEMM1: h1 = relu(z @ W1^T + b1) =================
    float acc1[2][8][4];
    #pragma unroll
    for (int a = 0; a < 2; a++)
        #pragma unroll
        for (int b = 0; b < 8; b++)
            #pragma unroll
            for (int c = 0; c < 4; c++) acc1[a][b][c] = 0.f;

    // z staging: LDG fp32 (prefetched 1 chunk ahead) -> split2 -> packed STS
    auto ldgz = [&](float* v, int kc) {
        int k0 = kc * 16 + (tid & 3) * 4;
        const float* src = z + (size_t)(m0 + (tid >> 2)) * 361 + k0;
        #pragma unroll
        for (int j = 0; j < 4; j++) v[j] = (k0 + j < 361) ? __ldg(src + j) : 0.f;
    };
    auto stsz = [&](int buf, const float* v) {
        unsigned h0, l0, h1, l1;
        split2(v[0], v[1], h0, l0);
        split2(v[2], v[3], h1, l1);
        unsigned* dst = smu + 33792 + buf * 1536 + (tid >> 2) * 12 + (tid & 3) * 2;
        *(uint2*)dst = make_uint2(h0, h1);
        *(uint2*)(dst + 3072) = make_uint2(l0, l1);
    };
    auto stage_w1 = [&](int buf, int kc) {
        int n = tid >> 1, q4 = (tid & 1) * 4;
        cpa16(smu + 39936 + buf * 3072 + n * 12 + q4, g_W1h + kc * 2048 + n * 8 + q4);
        cpa16(smu + 46080 + buf * 3072 + n * 12 + q4, g_W1l + kc * 2048 + n * 8 + q4);
    };

    const int w1_frag = (wn * 64 + brow) * 12 + bk4;
    const int z_fragA = (wm * 32 + arow) * 12 + ak4;

    float zv[4];
    ldgz(zv, 0); stsz(0, zv);      // chunk 0 staged directly
    ldgz(zv, 1);                   // prefetch chunk 1
    stage_w1(0, 0); cp_commit();

    for (int kc = 0; kc < NCH1; kc++) {
        if (kc + 1 < NCH1) {
            stsz((kc + 1) & 1, zv);                 // buf protected by trailing sync of kc-1
            stage_w1((kc + 1) & 1, kc + 1); cp_commit();
            if (kc + 2 < NCH1) ldgz(zv, kc + 2);    // prefetch next
            cp_wait<1>();
        } else {
            cp_wait<0>();
        }
        __syncthreads();
        unsigned a_addr  = sb + 4u * (33792 + (kc & 1) * 1536 + z_fragA);
        unsigned bh_addr = sb + 4u * (39936 + (kc & 1) * 3072 + w1_frag);
        unsigned Ah[2][4], Al[2][4];
        ldsm4(Ah[0][0], Ah[0][1], Ah[0][2], Ah[0][3], a_addr);
        ldsm4(Ah[1][0], Ah[1][1], Ah[1][2], Ah[1][3], a_addr + 4u * 192);
        ldsm4(Al[0][0], Al[0][1], Al[0][2], Al[0][3], a_addr + 4u * 3072);
        ldsm4(Al[1][0], Al[1][1], Al[1][2], Al[1][3], a_addr + 4u * (3072 + 192));
        #pragma unroll
        for (int p = 0; p < 4; p++) {
            unsigned bh[4], bl[4];
            ldsm4(bh[0], bh[1], bh[2], bh[3], bh_addr + 4u * (p * 16 * 12));
            ldsm4(bl[0], bl[1], bl[2], bl[3], bh_addr + 4u * (6144 + p * 16 * 12));
            MMA12(Ah[0], Ah[1], Al[0], Al[1], bh, bl, acc1[0][2*p], acc1[1][2*p]);
        }
        __syncthreads();
    }

    // prefetch W2 chunk 0
    auto stage2 = [&](int buf, int kc) {
        #pragma unroll
        for (int i = tid; i < 1024; i += 512) {
            int n = i >> 3, q4 = (i & 7) * 4;
            cpa16(smu + 33792 + buf * 4608 + n * 36 + q4, g_W2h + kc * 4096 + n * 32 + q4);
            cpa16(smu + 43008 + buf * 4608 + n * 36 + q4, g_W2l + kc * 4096 + n * 32 + q4);
        }
    };
    stage2(0, 0); cp_commit();

    // GEMM1 epilogue -> packed h1
    #pragma unroll
    for (int mt = 0; mt < 2; mt++) {
        #pragma unroll
        for (int nt = 0; nt < 8; nt++) {
            int m = wm * 32 + mt * 16 + g;
            int n = wn * 64 + nt * 8 + 2 * tg;
            int nu = n >> 1;
            float bv0 = __ldg(b1 + n), bv1 = __ldg(b1 + n + 1);
            unsigned hi, lo;
            split2(relu_(acc1[mt][nt][0] + bv0), relu_(acc1[mt][nt][1] + bv1), hi, lo);
            h1hi[m * 132 + nu] = hi; h1lo[m * 132 + nu] = lo;
            split2(relu_(acc1[mt][nt][2] + bv0), relu_(acc1[mt][nt][3] + bv1), hi, lo);
            h1hi[(m + 8) * 132 + nu] = hi; h1lo[(m + 8) * 132 + nu] = lo;
        }
    }
    __syncthreads();

    // ================= GEMM2 =================
    float acc2[2][4][4];
    #pragma unroll
    for (int a = 0; a < 2; a++)
        #pragma unroll
        for (int b = 0; b < 4; b++)
            #pragma unroll
            for (int c = 0; c < 4; c++) acc2[a][b][c] = 0.f;

    const int h1_fragA = (wm * 32 + arow) * 132 + ak4;
    const int w2_fragB = (wn * 32 + brow) * 36 + bk4;

    for (int kc = 0; kc < 4; kc++) {
        if (kc + 1 < 4) { stage2((kc + 1) & 1, kc + 1); cp_commit(); cp_wait<1>(); }
        else            { cp_wait<0>(); }
        __syncthreads();
        unsigned w2h_addr = sb + 4u * (33792 + (kc & 1) * 4608 + w2_fragB);
        unsigned w2l_addr = w2h_addr + 4u * 9216;
        #pragma unroll
        for (int q = 0; q < 4; q++) {
            int u0 = kc * 32 + q * 8;
            unsigned Ah[2][4], Al[2][4];
            ldsm4(Ah[0][0], Ah[0][1], Ah[0][2], Ah[0][3], sb + 4u * (h1_fragA + u0));
            ldsm4(Ah[1][0], Ah[1][1], Ah[1][2], Ah[1][3], sb + 4u * (h1_fragA + 16 * 132 + u0));
            ldsm4(Al[0][0], Al[0][1], Al[0][2], Al[0][3], sb + 4u * (16896 + h1_fragA + u0));
            ldsm4(Al[1][0], Al[1][1], Al[1][2], Al[1][3], sb + 4u * (16896 + h1_fragA + 16 * 132 + u0));
            #pragma unroll
            for (int p = 0; p < 2; p++) {
                unsigned bh[4], bl[4];
                ldsm4(bh[0], bh[1], bh[2], bh[3], w2h_addr + 4u * (p * 16 * 36 + q * 8));
                ldsm4(bl[0], bl[1], bl[2], bl[3], w2l_addr + 4u * (p * 16 * 36 + q * 8));
                MMA12(Ah[0], Ah[1], Al[0], Al[1], bh, bl, acc2[0][2*p], acc2[1][2*p]);
            }
        }
        __syncthreads();
    }

    // ---- stage W3 @8704/13056 + h2 epilogue @33792 ----
    unsigned* w3h = smu + 8704;   // [64][68]
    unsigned* w3l = smu + 13056;
    #pragma unroll
    for (int i = tid; i < 2048; i += 512) {
        int half = i >> 10, j = i & 1023;
        int n = j >> 4, q4 = (j & 15) * 4;
        cpa16((half ? w3l : w3h) + n * 68 + q4, (half ? g_W3l : g_W3h) + n * 64 + q4);
    }
    cp_commit();

    unsigned* h2hi = smu + 33792;  // [128][68]
    unsigned* h2lo = smu + 42496;
    #pragma unroll
    for (int mt = 0; mt < 2; mt++) {
        #pragma unroll
        for (int nt = 0; nt < 4; nt++) {
            int m = wm * 32 + mt * 16 + g;
            int n = wn * 32 + nt * 8 + 2 * tg;
            int nu = n >> 1;
            float bv0 = __ldg(b2 + n), bv1 = __ldg(b2 + n + 1);
            unsigned hi, lo;
            split2(relu_(acc2[mt][nt][0] + bv0), relu_(acc2[mt][nt][1] + bv1), hi, lo);
            h2hi[m * 68 + nu] = hi; h2lo[m * 68 + nu] = lo;
            split2(relu_(acc2[mt][nt][2] + bv0), relu_(acc2[mt][nt][3] + bv1), hi, lo);
            h2hi[(m + 8) * 68 + nu] = hi; h2lo[(m + 8) * 68 + nu] = lo;
        }
    }
    cp_wait<0>();
    __syncthreads();

    // ================= GEMM3 =================
    float acc3[2][2][4];
    #pragma unroll
    for (int a = 0; a < 2; a++)
        #pragma unroll
        for (int b = 0; b < 2; b++)
            #pragma unroll
            for (int c = 0; c < 4; c++) acc3[a][b][c] = 0.f;

    const int h2_fragA = 33792 + (wm * 32 + arow) * 68 + ak4;
    const int w3_fragB = 8704 + (wn * 16 + brow) * 68 + bk4;

    #pragma unroll
    for (int q = 0; q < 8; q++) {
        int u0 = q * 8;
        unsigned Ah[2][4], Al[2][4];
        ldsm4(Ah[0][0], Ah[0][1], Ah[0][2], Ah[0][3], sb + 4u * (h2_fragA + u0));
        ldsm4(Ah[1][0], Ah[1][1], Ah[1][2], Ah[1][3], sb + 4u * (h2_fragA + 16 * 68 + u0));
        ldsm4(Al[0][0], Al[0][1], Al[0][2], Al[0][3], sb + 4u * (8704 + h2_fragA + u0));
        ldsm4(Al[1][0], Al[1][1], Al[1][2], Al[1][3], sb + 4u * (8704 + h2_fragA + 16 * 68 + u0));
        unsigned bh[4], bl[4];
        ldsm4(bh[0], bh[1], bh[2], bh[3], sb + 4u * (w3_fragB + u0));
        ldsm4(bl[0], bl[1], bl[2], bl[3], sb + 4u * (4352 + w3_fragB + u0));
        MMA12(Ah[0], Ah[1], Al[0], Al[1], bh, bl, acc3[0][0], acc3[1][0]);
    }
    __syncthreads();   // all w3/h2 reads done before overwrite

    // ================= GRU setup =================
    unsigned* hhi  = smu;            // [128][36]
    unsigned* hlo  = smu + 4608;
    unsigned* whhh = smu + 9216;     // [208][36]
    unsigned* whhl = smu + 16704;
    float*    wih  = sm + 24192;     // [192][2]
    float*    sbrz = sm + 24576;     // [128]
    float*    sbin = sm + 24704;     // [64]
    float*    sbhn = sm + 24768;     // [64]
    float*    swo  = sm + 24832;     // [128]
    float*    sbo  = sm + 24960;     // [2]
    float*    x    = sm + 24964;     // [128][2]
    float*    xh   = sm + 25220;     // [128][20]

    #pragma unroll
    for (int i = tid; i < 3328; i += 512) {
        int half = (i >= 1664), j = half ? i - 1664 : i;
        int n = j >> 3, q4 = (j & 7) * 4;
        cpa16((half ? whhl : whhh) + n * 36 + q4, (half ? g_Whl : g_Whh) + n * 32 + q4);
    }
    cp_commit();
    if (tid < 384) wih[tid] = Wih[tid];
    if (tid < 128) sbrz[tid] = bih[tid] + bhh[tid];
    if (tid >= 128 && tid < 192) { sbin[tid - 128] = bih[tid]; sbhn[tid - 128] = bhh[tid]; }
    if (tid >= 192 && tid < 320) swo[tid - 192] = Wo[tid - 192];
    if (tid >= 320 && tid < 322) sbo[tid - 320] = bo[tid - 320];
    if (tid < 256) x[tid] = 0.f;

    // GEMM3 epilogue -> packed h
    #pragma unroll
    for (int mt = 0; mt < 2; mt++) {
        #pragma unroll
        for (int nt = 0; nt < 2; nt++) {
            int m = wm * 32 + mt * 16 + g;
            int n = wn * 16 + nt * 8 + 2 * tg;
            int nu = n >> 1;
            float bv0 = __ldg(b3 + n), bv1 = __ldg(b3 + n + 1);
            unsigned hi, lo;
            split2(relu_(acc3[mt][nt][0] + bv0), relu_(acc3[mt][nt][1] + bv1), hi, lo);
            hhi[m * 36 + nu] = hi; hlo[m * 36 + nu] = lo;
            split2(relu_(acc3[mt][nt][2] + bv0), relu_(acc3[mt][nt][3] + bv1), hi, lo);
            hhi[(m + 8) * 36 + nu] = hi; hlo[(m + 8) * 36 + nu] = lo;
        }
    }
    cp_wait<0>();
    __syncthreads();

    // ================= GRU loop: in-register gates =================
    const int h_fragA   = (wm * 32 + arow) * 36 + ak4;
    const int whh_fragB = 9216 + (wn * 48 + brow) * 36 + bk4;
    const int dx_fragB  = 9216 + (192 + brow) * 36 + bk4;
    const float4* wih4  = (const float4*)wih;
    const float2* sbrz2 = (const float2*)sbrz;
    const float2* sbin2 = (const float2*)sbin;
    const float2* sbhn2 = (const float2*)sbhn;

    for (int t = 0; t < PLEN; t++) {
        float acc[2][6][4];
        float accD[2][4];
        #pragma unroll
        for (int a = 0; a < 2; a++) {
            #pragma unroll
            for (int b = 0; b < 6; b++)
                #pragma unroll
                for (int c = 0; c < 4; c++) acc[a][b][c] = 0.f;
            #pragma unroll
            for (int c = 0; c < 4; c++) accD[a][c] = 0.f;
        }

        #pragma unroll
        for (int q = 0; q < 4; q++) {
            unsigned Ah[2][4], Al[2][4];
            ldsm4(Ah[0][0], Ah[0][1], Ah[0][2], Ah[0][3], sb + 4u * (h_fragA + q * 8));
            ldsm4(Ah[1][0], Ah[1][1], Ah[1][2], Ah[1][3], sb + 4u * (h_fragA + 16 * 36 + q * 8));
            ldsm4(Al[0][0], Al[0][1], Al[0][2], Al[0][3], sb + 4u * (4608 + h_fragA + q * 8));
            ldsm4(Al[1][0], Al[1][1], Al[1][2], Al[1][3], sb + 4u * (4608 + h_fragA + 16 * 36 + q * 8));
            #pragma unroll
            for (int p = 0; p < 3; p++) {
                unsigned bh[4], bl[4];
                ldsm4(bh[0], bh[1], bh[2], bh[3], sb + 4u * (whh_fragB + p * 16 * 36 + q * 8));
                ldsm4(bl[0], bl[1], bl[2], bl[3], sb + 4u * (7488 + whh_fragB + p * 16 * 36 + q * 8));
                MMA12(Ah[0], Ah[1], Al[0], Al[1], bh, bl, acc[0][2*p], acc[1][2*p]);
            }
            if (wn == 3) {  // dx tile (Wo rows 192-193; 194-207 zero)
                unsigned dh[4], dl[4];
                ldsm4(dh[0], dh[1], dh[2], dh[3], sb + 4u * (dx_fragB + q * 8));
                ldsm4(dl[0], dl[1], dl[2], dl[3], sb + 4u * (7488 + dx_fragB + q * 8));
                mma16(accD[0], Ah[0], dh[0], dh[1]);
                mma16(accD[1], Ah[1], dh[0], dh[1]);
                mma16(accD[0], Ah[0], dl[0], dl[1]);
                mma16(accD[1], Ah[1], dl[0], dl[1]);
                mma16(accD[0], Al[0], dh[0], dh[1]);
                mma16(accD[1], Al[1], dh[0], dh[1]);
            }
        }
        // x_{t-1} = x_{t-2} + h_{t-1}@Wo + bo  (cols 192,193 held by tg==0 lanes)
        if (t > 0 && wn == 3 && tg == 0) {
            float so0 = sbo[0], so1 = sbo[1];
            #pragma unroll
            for (int mt = 0; mt < 2; mt++) {
                #pragma unroll
                for (int sel = 0; sel < 2; sel++) {
                    int row = wm * 32 + mt * 16 + g + sel * 8;
                    float xv0 = x[2 * row]     + accD[mt][sel * 2]     + so0;
                    float xv1 = x[2 * row + 1] + accD[mt][sel * 2 + 1] + so1;
                    x[2 * row] = xv0; x[2 * row + 1] = xv1;
                    xh[row * 20 + (t - 1) * 2]     = xv0;
                    xh[row * 20 + (t - 1) * 2 + 1] = xv1;
                }
            }
        }
        __syncthreads();

        // gates from registers; h updated in place (thread owns its elements)
        #pragma unroll
        for (int mt = 0; mt < 2; mt++) {
            int r0 = wm * 32 + mt * 16 + g;
            #pragma unroll
            for (int b = 0; b < 2; b++) {
                int q = wn * 8 + b * 4 + tg;
                float4 wr = wih4[q], wz = wih4[32 + q], wnv = wih4[64 + q];
                float2 br = sbrz2[q], bz = sbrz2[32 + q];
                float2 bi = sbin2[q], bh2 = sbhn2[q];
                #pragma unroll
                for (int sel = 0; sel < 2; sel++) {
                    int row = r0 + sel * 8;
                    int ai = sel * 2;
                    float xv0 = x[2 * row], xv1 = x[2 * row + 1];
                    float rg0 = 0.5f * tanhapx(0.5f * (acc[mt][b][ai]     + xv0 * wr.x + xv1 * wr.y + br.x)) + 0.5f;
                    float rg1 = 0.5f * tanhapx(0.5f * (acc[mt][b][ai + 1] + xv0 * wr.z + xv1 * wr.w + br.y)) + 0.5f;
                    float zg0 = 0.5f * tanhapx(0.5f * (acc[mt][2 + b][ai]     + xv0 * wz.x + xv1 * wz.y + bz.x)) + 0.5f;
                    float zg1 = 0.5f * tanhapx(0.5f * (acc[mt][2 + b][ai + 1] + xv0 * wz.z + xv1 * wz.w + bz.y)) + 0.5f;
                    float ng0 = tanhapx(xv0 * wnv.x + xv1 * wnv.y + bi.x + rg0 * (acc[mt][4 + b][ai]     + bh2.x));
                    float ng1 = tanhapx(xv0 * wnv.z + xv1 * wnv.w + bi.y + rg1 * (acc[mt][4 + b][ai + 1] + bh2.y));
                    unsigned uh = hhi[row * 36 + q], ul = hlo[row * 36 + q];
                    float h0 = bflo(uh) + bflo(ul);
                    float h1 = bfhi(uh) + bfhi(ul);
                    float hn0 = (1.f - zg0) * ng0 + zg0 * h0;
                    float hn1 = (1.f - zg1) * ng1 + zg1 * h1;
                    unsigned nh, nl;
                    split2(hn0, hn1, nh, nl);
                    hhi[row * 36 + q] = nh; hlo[row * 36 + q] = nl;
                }
            }
        }
        __syncthreads();
    }

    // final Wo (step PLEN-1)
    if (tid < 256) {
        int r = tid >> 1, o = tid & 1;
        float s = sbo[o];
        const float* wr = swo + o * 64;
        #pragma unroll 8
        for (int c = 0; c < 32; c++) {
            unsigned uh = hhi[r * 36 + c], ul = hlo[r * 36 + c];
            s += (bflo(uh) + bflo(ul)) * wr[2 * c];
            s += (bfhi(uh) + bfhi(ul)) * wr[2 * c + 1];
        }
        float xv = x[r * 2 + o] + s;
        xh[r * 20 + (PLEN - 1) * 2 + o] = xv;
    }
    __syncthreads();

    // coalesced output: out[b, t, o]
    #pragma unroll
    for (int i = tid; i < 640; i += 512) {
        int r = i / 5, q = (i % 5) * 4;
        *(float4*)&out[(size_t)(m0 + r) * 20 + q] = *(const float4*)&xh[r * 20 + q];
    }
}

// ---------------------------------------------------------------------------
extern "C" void kernel_launch(void* const* d_in, const int* in_sizes, int n_in,
                              void* d_out, int out_size)
{
    const float* z   = (const float*)d_in[0];
    const float* W1  = (const float*)d_in[1];
    const float* b1  = (const float*)d_in[2];
    const float* W2  = (const float*)d_in[3];
    const float* b2  = (const float*)d_in[4];
    const float* W3  = (const float*)d_in[5];
    const float* b3  = (const float*)d_in[6];
    const float* Wih = (const float*)d_in[7];
    const float* Whh = (const float*)d_in[8];
    const float* bih = (const float*)d_in[9];
    const float* bhh = (const float*)d_in[10];
    const float* Wo  = (const float*)d_in[11];
    const float* bo  = (const float*)d_in[12];
    float* out = (float*)d_out;

    const int smem = 52224 * 4;  // 208896 B
    cudaFuncSetAttribute(fused_kernel, cudaFuncAttributeMaxDynamicSharedMemorySize, smem);

    prep_kernel<<<290, 256>>>(W1, W2, W3, Whh, Wo);
    fused_kernel<<<BS / 128, 512, smem>>>(z, b1, b2, b3, Wih, bih, bhh, Wo, bo, out);
}